// round 1
// baseline (speedup 1.0000x reference)
#include <cuda_runtime.h>
#include <math.h>

// Problem constants
#define B_    2
#define S_    2048
#define D_    4096
#define NH    32
#define NKV   8
#define HD    128
#define MTOK  (B_*S_)          // 4096 tokens
#define KVDIM (NKV*HD)         // 1024
#define ROPE_THETA 500000.0

// -------------------- scratch (device globals; no allocs allowed) -----------
__device__ float g_q [(size_t)MTOK * D_];     // Q after proj (+rope), [tok][NH*HD]
__device__ float g_k [(size_t)MTOK * KVDIM];  // K after proj (+rope), [tok][NKV*HD]
__device__ float g_v [(size_t)MTOK * KVDIM];  // V
__device__ float g_ao[(size_t)MTOK * D_];     // attention output [tok][NH*HD]
__device__ float g_cos[4096 * 64];
__device__ float g_sin[4096 * 64];

// -------------------- RoPE table (double precision trig) --------------------
__global__ void rope_table_kernel() {
    int idx = blockIdx.x * blockDim.x + threadIdx.x;
    if (idx >= 4096 * 64) return;
    int p = idx >> 6;
    int i = idx & 63;
    double inv = exp(-((double)(2 * i) / (double)HD) * log(ROPE_THETA));
    double ang = (double)p * inv;
    g_cos[idx] = (float)cos(ang);
    g_sin[idx] = (float)sin(ang);
}

// -------------------- RoPE apply (in place) ----------------------------------
__global__ void rope_apply_kernel(float* __restrict__ x, const int* __restrict__ pos,
                                  int nheads) {
    int idx = blockIdx.x * blockDim.x + threadIdx.x;
    int total = MTOK * nheads * 64;
    if (idx >= total) return;
    int i = idx & 63;
    int rem = idx >> 6;
    int h = rem % nheads;
    int t = rem / nheads;
    int p = pos[t];
    float c = g_cos[p * 64 + i];
    float s = g_sin[p * 64 + i];
    size_t off = (size_t)t * (nheads * HD) + h * HD + 2 * i;
    float a = x[off];
    float b = x[off + 1];
    x[off]     = a * c - b * s;
    x[off + 1] = a * s + b * c;
}

// -------------------- SGEMM: C = A(MxK) * B(KxN), row-major ------------------
// 128x128 block tile, BK=16, 8x8 per thread, 256 threads.
__global__ __launch_bounds__(256) void sgemm_kernel(
    const float* __restrict__ A, const float* __restrict__ Bm,
    float* __restrict__ C, int M, int N, int K)
{
    __shared__ __align__(16) float As[16][128];   // transposed: As[k][m]
    __shared__ __align__(16) float Bs[16][128];   // Bs[k][n]

    const int tid = threadIdx.x;
    const int tx = tid & 15;          // n direction
    const int ty = tid >> 4;          // m direction
    const int m0 = blockIdx.y * 128;
    const int n0 = blockIdx.x * 128;

    float acc[8][8];
#pragma unroll
    for (int i = 0; i < 8; i++)
#pragma unroll
        for (int j = 0; j < 8; j++) acc[i][j] = 0.f;

    for (int k0 = 0; k0 < K; k0 += 16) {
        // Load A tile (128 rows x 16 cols), 512 float4, 2 per thread, transpose
#pragma unroll
        for (int v = 0; v < 2; v++) {
            int f = tid * 2 + v;
            int row = f >> 2;
            int c4  = f & 3;
            float4 val = *(const float4*)(A + (size_t)(m0 + row) * K + k0 + c4 * 4);
            As[c4 * 4 + 0][row] = val.x;
            As[c4 * 4 + 1][row] = val.y;
            As[c4 * 4 + 2][row] = val.z;
            As[c4 * 4 + 3][row] = val.w;
        }
        // Load B tile (16 rows x 128 cols)
#pragma unroll
        for (int v = 0; v < 2; v++) {
            int f = tid * 2 + v;
            int row = f >> 5;
            int c4  = f & 31;
            float4 val = *(const float4*)(Bm + (size_t)(k0 + row) * N + n0 + c4 * 4);
            *(float4*)(&Bs[row][c4 * 4]) = val;
        }
        __syncthreads();

#pragma unroll
        for (int k = 0; k < 16; k++) {
            float ra[8], rb[8];
            *(float4*)(&ra[0]) = *(const float4*)(&As[k][ty * 8]);
            *(float4*)(&ra[4]) = *(const float4*)(&As[k][ty * 8 + 4]);
            *(float4*)(&rb[0]) = *(const float4*)(&Bs[k][tx * 8]);
            *(float4*)(&rb[4]) = *(const float4*)(&Bs[k][tx * 8 + 4]);
#pragma unroll
            for (int i = 0; i < 8; i++)
#pragma unroll
                for (int j = 0; j < 8; j++)
                    acc[i][j] = fmaf(ra[i], rb[j], acc[i][j]);
        }
        __syncthreads();
    }

#pragma unroll
    for (int i = 0; i < 8; i++) {
        float* crow = C + (size_t)(m0 + ty * 8 + i) * N + n0 + tx * 8;
        *(float4*)(crow)     = make_float4(acc[i][0], acc[i][1], acc[i][2], acc[i][3]);
        *(float4*)(crow + 4) = make_float4(acc[i][4], acc[i][5], acc[i][6], acc[i][7]);
    }
}

// -------------------- Flash attention (fp32, causal, GQA) --------------------
// Br=Bc=64, 256 threads. grid = (S/64, NH, B)
#define QSTRIDE 132                    // HD + 4 pad (keeps float4 alignment)
#define PSTRIDE 65
#define FLASH_SMEM_FLOATS (3*64*QSTRIDE + 64*PSTRIDE + 3*64)
#define FLASH_SMEM_BYTES  (FLASH_SMEM_FLOATS * 4)

__global__ __launch_bounds__(256) void flash_kernel(
    const float* __restrict__ Q, const float* __restrict__ K,
    const float* __restrict__ V, const float* __restrict__ amask,
    float* __restrict__ O)
{
    extern __shared__ __align__(16) float sm[];
    float* sQ = sm;                         // [64][QSTRIDE]
    float* sK = sQ + 64 * QSTRIDE;
    float* sV = sK + 64 * QSTRIDE;
    float* sP = sV + 64 * QSTRIDE;          // [64][PSTRIDE]
    float* sM = sP + 64 * PSTRIDE;
    float* sL = sM + 64;
    float* sC = sL + 64;

    const int qt = blockIdx.x;
    const int h  = blockIdx.y;
    const int b  = blockIdx.z;
    const int kvh = h >> 2;                 // n_rep = 4
    const int tid = threadIdx.x;
    const int tx = tid & 15;
    const int ty = tid >> 4;
    const float scale = 0.08838834764831845f;   // 1/sqrt(128)

    // Load Q tile (scaled)
    {
        const float* gq = Q + (size_t)(b * S_ + qt * 64) * D_ + h * HD;
#pragma unroll
        for (int u = 0; u < 8; u++) {
            int f = u * 256 + tid;
            int r = f >> 5;
            int c4 = f & 31;
            float4 val = *(const float4*)(gq + (size_t)r * D_ + c4 * 4);
            val.x *= scale; val.y *= scale; val.z *= scale; val.w *= scale;
            *(float4*)(sQ + r * QSTRIDE + c4 * 4) = val;
        }
    }
    if (tid < 64) { sM[tid] = -INFINITY; sL[tid] = 0.f; }

    float acc[4][8];
#pragma unroll
    for (int i = 0; i < 4; i++)
#pragma unroll
        for (int j = 0; j < 8; j++) acc[i][j] = 0.f;

    __syncthreads();

    const float* mrow = amask + (size_t)b * S_;

    for (int kt = 0; kt <= qt; kt++) {
        __syncthreads();   // previous PV / sP reads done before overwrite
        // Load K, V tiles
        {
            const float* gk = K + (size_t)(b * S_ + kt * 64) * KVDIM + kvh * HD;
            const float* gv = V + (size_t)(b * S_ + kt * 64) * KVDIM + kvh * HD;
#pragma unroll
            for (int u = 0; u < 8; u++) {
                int f = u * 256 + tid;
                int r = f >> 5;
                int c4 = f & 31;
                *(float4*)(sK + r * QSTRIDE + c4 * 4) =
                    *(const float4*)(gk + (size_t)r * KVDIM + c4 * 4);
                *(float4*)(sV + r * QSTRIDE + c4 * 4) =
                    *(const float4*)(gv + (size_t)r * KVDIM + c4 * 4);
            }
        }
        __syncthreads();

        // S = Q * K^T  (64x64), per-thread 4x4
        float sacc[4][4];
#pragma unroll
        for (int i = 0; i < 4; i++)
#pragma unroll
            for (int j = 0; j < 4; j++) sacc[i][j] = 0.f;

#pragma unroll 8
        for (int k4 = 0; k4 < 32; k4++) {
            float4 a[4], bb[4];
#pragma unroll
            for (int i = 0; i < 4; i++)
                a[i] = *(const float4*)(sQ + (ty * 4 + i) * QSTRIDE + k4 * 4);
#pragma unroll
            for (int j = 0; j < 4; j++)
                bb[j] = *(const float4*)(sK + (tx * 4 + j) * QSTRIDE + k4 * 4);
#pragma unroll
            for (int i = 0; i < 4; i++)
#pragma unroll
                for (int j = 0; j < 4; j++) {
                    sacc[i][j] = fmaf(a[i].x, bb[j].x, sacc[i][j]);
                    sacc[i][j] = fmaf(a[i].y, bb[j].y, sacc[i][j]);
                    sacc[i][j] = fmaf(a[i].z, bb[j].z, sacc[i][j]);
                    sacc[i][j] = fmaf(a[i].w, bb[j].w, sacc[i][j]);
                }
        }
#pragma unroll
        for (int i = 0; i < 4; i++)
#pragma unroll
            for (int j = 0; j < 4; j++)
                sP[(ty * 4 + i) * PSTRIDE + tx * 4 + j] = sacc[i][j];
        __syncthreads();

        // Online softmax row pass (64 rows, one thread each)
        if (tid < 64) {
            int r = tid;
            int gq_idx = qt * 64 + r;
            float mx = sM[r];
            for (int j = 0; j < 64; j++) {
                int kk = kt * 64 + j;
                float vv = sP[r * PSTRIDE + j];
                bool valid = (kk <= gq_idx) && (mrow[kk] > 0.f);
                vv = valid ? vv : -1e30f;
                sP[r * PSTRIDE + j] = vv;
                mx = fmaxf(mx, vv);
            }
            float m_new = mx;
            float corr = expf(sM[r] - m_new);
            float sum = 0.f;
            for (int j = 0; j < 64; j++) {
                float p = expf(sP[r * PSTRIDE + j] - m_new);
                sP[r * PSTRIDE + j] = p;
                sum += p;
            }
            sL[r] = sL[r] * corr + sum;
            sM[r] = m_new;
            sC[r] = corr;
        }
        __syncthreads();

        // Rescale + PV accumulate: O(64x128), per-thread 4x8
        float cc[4];
#pragma unroll
        for (int i = 0; i < 4; i++) cc[i] = sC[ty * 4 + i];
#pragma unroll
        for (int i = 0; i < 4; i++)
#pragma unroll
            for (int j = 0; j < 8; j++) acc[i][j] *= cc[i];

#pragma unroll 8
        for (int k = 0; k < 64; k++) {
            float a[4];
#pragma unroll
            for (int i = 0; i < 4; i++) a[i] = sP[(ty * 4 + i) * PSTRIDE + k];
            float4 v0 = *(const float4*)(sV + k * QSTRIDE + tx * 8);
            float4 v1 = *(const float4*)(sV + k * QSTRIDE + tx * 8 + 4);
#pragma unroll
            for (int i = 0; i < 4; i++) {
                acc[i][0] = fmaf(a[i], v0.x, acc[i][0]);
                acc[i][1] = fmaf(a[i], v0.y, acc[i][1]);
                acc[i][2] = fmaf(a[i], v0.z, acc[i][2]);
                acc[i][3] = fmaf(a[i], v0.w, acc[i][3]);
                acc[i][4] = fmaf(a[i], v1.x, acc[i][4]);
                acc[i][5] = fmaf(a[i], v1.y, acc[i][5]);
                acc[i][6] = fmaf(a[i], v1.z, acc[i][6]);
                acc[i][7] = fmaf(a[i], v1.w, acc[i][7]);
            }
        }
    }

    // Normalize + write out
#pragma unroll
    for (int i = 0; i < 4; i++) {
        float invl = 1.f / sL[ty * 4 + i];
        float* orow = O + (size_t)(b * S_ + qt * 64 + ty * 4 + i) * D_ + h * HD + tx * 8;
        *(float4*)(orow)     = make_float4(acc[i][0] * invl, acc[i][1] * invl,
                                           acc[i][2] * invl, acc[i][3] * invl);
        *(float4*)(orow + 4) = make_float4(acc[i][4] * invl, acc[i][5] * invl,
                                           acc[i][6] * invl, acc[i][7] * invl);
    }
}

// -------------------- launch ---------------------------------------------------
extern "C" void kernel_launch(void* const* d_in, const int* in_sizes, int n_in,
                              void* d_out, int out_size)
{
    const float* x     = (const float*)d_in[0];
    const float* amask = (const float*)d_in[1];
    const int*   pos   = (const int*)  d_in[2];
    const float* wq    = (const float*)d_in[3];
    const float* wk    = (const float*)d_in[4];
    const float* wv    = (const float*)d_in[5];
    const float* wo    = (const float*)d_in[6];
    float* out = (float*)d_out;

    float *q, *k, *v, *ao;
    cudaGetSymbolAddress((void**)&q,  g_q);
    cudaGetSymbolAddress((void**)&k,  g_k);
    cudaGetSymbolAddress((void**)&v,  g_v);
    cudaGetSymbolAddress((void**)&ao, g_ao);

    // RoPE tables
    rope_table_kernel<<<(4096 * 64 + 255) / 256, 256>>>();

    // QKV projections
    sgemm_kernel<<<dim3(D_ / 128, MTOK / 128), 256>>>(x, wq, q, MTOK, D_,    D_);
    sgemm_kernel<<<dim3(KVDIM / 128, MTOK / 128), 256>>>(x, wk, k, MTOK, KVDIM, D_);
    sgemm_kernel<<<dim3(KVDIM / 128, MTOK / 128), 256>>>(x, wv, v, MTOK, KVDIM, D_);

    // RoPE
    rope_apply_kernel<<<(MTOK * NH  * 64 + 255) / 256, 256>>>(q, pos, NH);
    rope_apply_kernel<<<(MTOK * NKV * 64 + 255) / 256, 256>>>(k, pos, NKV);

    // Attention
    cudaFuncSetAttribute(flash_kernel, cudaFuncAttributeMaxDynamicSharedMemorySize,
                         FLASH_SMEM_BYTES);
    flash_kernel<<<dim3(S_ / 64, NH, B_), 256, FLASH_SMEM_BYTES>>>(q, k, v, amask, ao);

    // Output projection
    sgemm_kernel<<<dim3(D_ / 128, MTOK / 128), 256>>>(ao, wo, out, MTOK, D_, D_);
}

// round 4
// speedup vs baseline: 1.7830x; 1.7830x over previous
#include <cuda_runtime.h>
#include <cuda_bf16.h>
#include <cstdint>
#include <math.h>

// Problem constants
#define B_    2
#define S_    2048
#define D_    4096
#define NH    32
#define NKV   8
#define HD    128
#define MTOK  (B_*S_)          // 4096 tokens
#define KVDIM (NKV*HD)         // 1024
#define K3    12288            // 3 * 4096 (split-precision stacked K)
#define ROPE_THETA 500000.0

// -------------------- scratch (device globals; no allocs allowed) -----------
__device__ float g_q [(size_t)MTOK * D_];
__device__ float g_k [(size_t)MTOK * KVDIM];
__device__ float g_v [(size_t)MTOK * KVDIM];
__device__ float g_ao[(size_t)MTOK * D_];
__device__ float g_cos[4096 * 64];
__device__ float g_sin[4096 * 64];
__device__ __nv_bfloat16 g_Abf[(size_t)MTOK * K3];
__device__ __nv_bfloat16 g_Wbf[(size_t)(D_ + KVDIM + KVDIM + D_) * K3];

// =====================  PTX helpers (baseline ISA only)  ====================
__device__ __forceinline__ uint32_t smem_u32(const void* p) {
    uint32_t a;
    asm("{ .reg .u64 t; cvta.to.shared.u64 t, %1; cvt.u32.u64 %0, t; }" : "=r"(a) : "l"(p));
    return a;
}
__device__ __forceinline__ void cp_async16(uint32_t s, const void* g) {
    asm volatile("cp.async.cg.shared.global [%0], [%1], 16;" :: "r"(s), "l"(g));
}
__device__ __forceinline__ void cp_commit() {
    asm volatile("cp.async.commit_group;" ::: "memory");
}
template<int N_> __device__ __forceinline__ void cp_wait() {
    asm volatile("cp.async.wait_group %0;" :: "n"(N_) : "memory");
}
__device__ __forceinline__ void ldmatrix_x4(uint32_t* r, uint32_t addr) {
    asm volatile("ldmatrix.sync.aligned.m8n8.x4.shared.b16 {%0,%1,%2,%3}, [%4];"
                 : "=r"(r[0]), "=r"(r[1]), "=r"(r[2]), "=r"(r[3]) : "r"(addr));
}
__device__ __forceinline__ void ldmatrix_x2(uint32_t* r, uint32_t addr) {
    asm volatile("ldmatrix.sync.aligned.m8n8.x2.shared.b16 {%0,%1}, [%2];"
                 : "=r"(r[0]), "=r"(r[1]) : "r"(addr));
}
__device__ __forceinline__ void mma_16816(float* d, const uint32_t* a, const uint32_t* b) {
    asm volatile(
        "mma.sync.aligned.m16n8k16.row.col.f32.bf16.bf16.f32 "
        "{%0,%1,%2,%3}, {%4,%5,%6,%7}, {%8,%9}, {%0,%1,%2,%3};"
        : "+f"(d[0]), "+f"(d[1]), "+f"(d[2]), "+f"(d[3])
        : "r"(a[0]), "r"(a[1]), "r"(a[2]), "r"(a[3]), "r"(b[0]), "r"(b[1]));
}

// =====================  conversion kernels  =================================
// X[4096][4096] fp32 -> Y[4096][12288] bf16: [0,4096)=hi, [4096,8192)=lo, [8192,12288)=hi
__global__ __launch_bounds__(256) void convert_a_kernel(const float* __restrict__ X,
                                                        __nv_bfloat16* __restrict__ Y) {
    int i = blockIdx.x * blockDim.x + threadIdx.x;
    int row = i >> 10;
    int col = (i & 1023) << 2;
    float4 v = ((const float4*)X)[i];
    __nv_bfloat16 hx = __float2bfloat16_rn(v.x);
    __nv_bfloat16 hy = __float2bfloat16_rn(v.y);
    __nv_bfloat16 hz = __float2bfloat16_rn(v.z);
    __nv_bfloat16 hw = __float2bfloat16_rn(v.w);
    __nv_bfloat16 lx = __float2bfloat16_rn(v.x - __bfloat162float(hx));
    __nv_bfloat16 ly = __float2bfloat16_rn(v.y - __bfloat162float(hy));
    __nv_bfloat16 lz = __float2bfloat16_rn(v.z - __bfloat162float(hz));
    __nv_bfloat16 lw = __float2bfloat16_rn(v.w - __bfloat162float(hw));
    size_t base = (size_t)row * K3 + col;
    __nv_bfloat162 h01 = __halves2bfloat162(hx, hy);
    __nv_bfloat162 h23 = __halves2bfloat162(hz, hw);
    __nv_bfloat162 l01 = __halves2bfloat162(lx, ly);
    __nv_bfloat162 l23 = __halves2bfloat162(lz, lw);
    ((__nv_bfloat162*)(Y + base))[0] = h01;
    ((__nv_bfloat162*)(Y + base))[1] = h23;
    ((__nv_bfloat162*)(Y + base + 4096))[0] = l01;
    ((__nv_bfloat162*)(Y + base + 4096))[1] = l23;
    ((__nv_bfloat162*)(Y + base + 8192))[0] = h01;
    ((__nv_bfloat162*)(Y + base + 8192))[1] = h23;
}

// W[K=4096][N] fp32 -> Y[N][12288] bf16 (transposed): [0,4096)=hi, [4096,8192)=hi, [8192,12288)=lo
__global__ __launch_bounds__(256) void convert_w_kernel(const float* __restrict__ W,
                                                        __nv_bfloat16* __restrict__ Y, int N) {
    __shared__ float t[32][33];
    int n0 = blockIdx.x * 32;
    int k0 = blockIdx.y * 32;
    int tx = threadIdx.x;
    int ty = threadIdx.y;
#pragma unroll
    for (int i = 0; i < 4; i++)
        t[ty + 8 * i][tx] = W[(size_t)(k0 + ty + 8 * i) * N + n0 + tx];
    __syncthreads();
#pragma unroll
    for (int i = 0; i < 4; i++) {
        int r = ty + 8 * i;
        float v = t[tx][r];
        __nv_bfloat16 hi = __float2bfloat16_rn(v);
        __nv_bfloat16 lo = __float2bfloat16_rn(v - __bfloat162float(hi));
        size_t base = (size_t)(n0 + r) * K3 + k0 + tx;
        Y[base] = hi;
        Y[base + 4096] = hi;
        Y[base + 8192] = lo;
    }
}

// =====================  mma.sync bf16 GEMM  =================================
// C[M][N] = A[M][K3] * Bt[N][K3]^T, fp32 accumulate in registers.
// CTA 128x128, BK=64, 3-stage cp.async, 8 warps (2m x 4n), warp tile 64x32.
#define BKK 64
#define NST 3
#define STAGE_BYTES 32768                 // A 16KB + B 16KB
#define GEMM_SMEM (NST * STAGE_BYTES)     // 96KB

__device__ __forceinline__ void gemm_load_stage(
    const __nv_bfloat16* __restrict__ A, const __nv_bfloat16* __restrict__ Bt,
    int m0, int n0, int it, uint32_t sA, int tid)
{
    int k0 = it * BKK;
    uint32_t sB = sA + 16384u;
#pragma unroll
    for (int u = 0; u < 4; u++) {
        int f = u * 256 + tid;
        int r = f >> 3;              // row 0..127
        int c = f & 7;               // 16B chunk 0..7 (row = 128B)
        uint32_t sw = (uint32_t)(c ^ (r & 7));
        cp_async16(sA + (uint32_t)r * 128u + sw * 16u,
                   A + (size_t)(m0 + r) * K3 + k0 + c * 8);
    }
#pragma unroll
    for (int u = 0; u < 4; u++) {
        int f = u * 256 + tid;
        int r = f >> 3;
        int c = f & 7;
        uint32_t sw = (uint32_t)(c ^ (r & 7));
        cp_async16(sB + (uint32_t)r * 128u + sw * 16u,
                   Bt + (size_t)(n0 + r) * K3 + k0 + c * 8);
    }
    cp_commit();
}

__global__ __launch_bounds__(256) void gemm_bf16_kernel(
    const __nv_bfloat16* __restrict__ A, const __nv_bfloat16* __restrict__ Bt,
    float* __restrict__ C, int N)
{
    extern __shared__ __align__(1024) char gsm[];
    const uint32_t sbase = smem_u32(gsm);
    const int tid  = threadIdx.x;
    const int wid  = tid >> 5;
    const int lane = tid & 31;

    const int m0 = blockIdx.y * 128;
    const int n0 = blockIdx.x * 128;
    const int wm = (wid >> 2) * 64;      // warp m offset in tile
    const int wn = (wid & 3) * 32;       // warp n offset in tile

    float acc[4][4][4];
#pragma unroll
    for (int i = 0; i < 4; i++)
#pragma unroll
        for (int j = 0; j < 4; j++)
#pragma unroll
            for (int e = 0; e < 4; e++) acc[i][j][e] = 0.f;

    const int iters = K3 / BKK;          // 192
    gemm_load_stage(A, Bt, m0, n0, 0, sbase + 0u * STAGE_BYTES, tid);
    gemm_load_stage(A, Bt, m0, n0, 1, sbase + 1u * STAGE_BYTES, tid);

    // precomputed per-lane ldmatrix row/chunk components
    const int a_row_in16 = ((lane >> 3) & 1) * 8 + (lane & 7);  // 0..15
    const int a_cadd     = lane >> 4;                            // 0 or 1 (k chunk select)
    const int b_row_in8  = lane & 7;
    const int b_cadd     = (lane >> 3) & 1;

    for (int it = 0; it < iters; it++) {
        cp_wait<1>();
        __syncthreads();
        if (it + 2 < iters)
            gemm_load_stage(A, Bt, m0, n0, it + 2,
                            sbase + (uint32_t)((it + 2) % NST) * STAGE_BYTES, tid);

        uint32_t sA = sbase + (uint32_t)(it % NST) * STAGE_BYTES;
        uint32_t sB = sA + 16384u;

#pragma unroll
        for (int ks = 0; ks < 4; ks++) {
            int c0 = ks * 2;
            uint32_t afr[4][4];
#pragma unroll
            for (int im = 0; im < 4; im++) {
                int r  = wm + im * 16 + a_row_in16;
                int cc = c0 + a_cadd;
                uint32_t addr = sA + (uint32_t)r * 128u + (uint32_t)((cc ^ (r & 7)) * 16);
                ldmatrix_x4(afr[im], addr);
            }
            uint32_t bfr[4][2];
#pragma unroll
            for (int jn = 0; jn < 4; jn++) {
                int r  = wn + jn * 8 + b_row_in8;
                int cc = c0 + b_cadd;
                uint32_t addr = sB + (uint32_t)r * 128u + (uint32_t)((cc ^ (r & 7)) * 16);
                ldmatrix_x2(bfr[jn], addr);
            }
#pragma unroll
            for (int im = 0; im < 4; im++)
#pragma unroll
                for (int jn = 0; jn < 4; jn++)
                    mma_16816(acc[im][jn], afr[im], bfr[jn]);
        }
    }

    // epilogue: write fragments
    const int tg = lane >> 2;      // row within 8
    const int tc = lane & 3;       // col pair
#pragma unroll
    for (int im = 0; im < 4; im++) {
#pragma unroll
        for (int jn = 0; jn < 4; jn++) {
            int row = m0 + wm + im * 16 + tg;
            int col = n0 + wn + jn * 8 + tc * 2;
            float2 v0 = make_float2(acc[im][jn][0], acc[im][jn][1]);
            float2 v1 = make_float2(acc[im][jn][2], acc[im][jn][3]);
            *(float2*)(C + (size_t)row * N + col) = v0;
            *(float2*)(C + (size_t)(row + 8) * N + col) = v1;
        }
    }
}

// =====================  RoPE  ===============================================
__global__ void rope_table_kernel() {
    int idx = blockIdx.x * blockDim.x + threadIdx.x;
    if (idx >= 4096 * 64) return;
    int p = idx >> 6;
    int i = idx & 63;
    double inv = exp(-((double)(2 * i) / (double)HD) * log(ROPE_THETA));
    double ang = (double)p * inv;
    g_cos[idx] = (float)cos(ang);
    g_sin[idx] = (float)sin(ang);
}

__global__ void rope_apply_kernel(float* __restrict__ x, const int* __restrict__ pos,
                                  int nheads) {
    int idx = blockIdx.x * blockDim.x + threadIdx.x;
    int total = MTOK * nheads * 64;
    if (idx >= total) return;
    int i = idx & 63;
    int rem = idx >> 6;
    int h = rem % nheads;
    int t = rem / nheads;
    int p = pos[t];
    float c = g_cos[p * 64 + i];
    float s = g_sin[p * 64 + i];
    size_t off = (size_t)t * (nheads * HD) + h * HD + 2 * i;
    float a = x[off];
    float b = x[off + 1];
    x[off]     = a * c - b * s;
    x[off + 1] = a * s + b * c;
}

// =====================  Flash attention (fp32, causal, GQA) =================
#define QSTRIDE 132
#define PSTRIDE 65
#define FLASH_SMEM_FLOATS (3*64*QSTRIDE + 64*PSTRIDE + 3*64)
#define FLASH_SMEM_BYTES  (FLASH_SMEM_FLOATS * 4)

__global__ __launch_bounds__(256) void flash_kernel(
    const float* __restrict__ Q, const float* __restrict__ K,
    const float* __restrict__ V, const float* __restrict__ amask,
    float* __restrict__ O)
{
    extern __shared__ __align__(16) float sm[];
    float* sQ = sm;
    float* sK = sQ + 64 * QSTRIDE;
    float* sV = sK + 64 * QSTRIDE;
    float* sP = sV + 64 * QSTRIDE;
    float* sM = sP + 64 * PSTRIDE;
    float* sL = sM + 64;
    float* sC = sL + 64;

    const int qt = blockIdx.x;
    const int h  = blockIdx.y;
    const int b  = blockIdx.z;
    const int kvh = h >> 2;
    const int tid = threadIdx.x;
    const int tx = tid & 15;
    const int ty = tid >> 4;
    const float scale = 0.08838834764831845f;

    {
        const float* gq = Q + (size_t)(b * S_ + qt * 64) * D_ + h * HD;
#pragma unroll
        for (int u = 0; u < 8; u++) {
            int f = u * 256 + tid;
            int r = f >> 5;
            int c4 = f & 31;
            float4 val = *(const float4*)(gq + (size_t)r * D_ + c4 * 4);
            val.x *= scale; val.y *= scale; val.z *= scale; val.w *= scale;
            *(float4*)(sQ + r * QSTRIDE + c4 * 4) = val;
        }
    }
    if (tid < 64) { sM[tid] = -INFINITY; sL[tid] = 0.f; }

    float acc[4][8];
#pragma unroll
    for (int i = 0; i < 4; i++)
#pragma unroll
        for (int j = 0; j < 8; j++) acc[i][j] = 0.f;

    __syncthreads();

    const float* mrow = amask + (size_t)b * S_;

    for (int kt = 0; kt <= qt; kt++) {
        __syncthreads();
        {
            const float* gk = K + (size_t)(b * S_ + kt * 64) * KVDIM + kvh * HD;
            const float* gv = V + (size_t)(b * S_ + kt * 64) * KVDIM + kvh * HD;
#pragma unroll
            for (int u = 0; u < 8; u++) {
                int f = u * 256 + tid;
                int r = f >> 5;
                int c4 = f & 31;
                *(float4*)(sK + r * QSTRIDE + c4 * 4) =
                    *(const float4*)(gk + (size_t)r * KVDIM + c4 * 4);
                *(float4*)(sV + r * QSTRIDE + c4 * 4) =
                    *(const float4*)(gv + (size_t)r * KVDIM + c4 * 4);
            }
        }
        __syncthreads();

        float sacc[4][4];
#pragma unroll
        for (int i = 0; i < 4; i++)
#pragma unroll
            for (int j = 0; j < 4; j++) sacc[i][j] = 0.f;

#pragma unroll 8
        for (int k4 = 0; k4 < 32; k4++) {
            float4 a[4], bb[4];
#pragma unroll
            for (int i = 0; i < 4; i++)
                a[i] = *(const float4*)(sQ + (ty * 4 + i) * QSTRIDE + k4 * 4);
#pragma unroll
            for (int j = 0; j < 4; j++)
                bb[j] = *(const float4*)(sK + (tx * 4 + j) * QSTRIDE + k4 * 4);
#pragma unroll
            for (int i = 0; i < 4; i++)
#pragma unroll
                for (int j = 0; j < 4; j++) {
                    sacc[i][j] = fmaf(a[i].x, bb[j].x, sacc[i][j]);
                    sacc[i][j] = fmaf(a[i].y, bb[j].y, sacc[i][j]);
                    sacc[i][j] = fmaf(a[i].z, bb[j].z, sacc[i][j]);
                    sacc[i][j] = fmaf(a[i].w, bb[j].w, sacc[i][j]);
                }
        }
#pragma unroll
        for (int i = 0; i < 4; i++)
#pragma unroll
            for (int j = 0; j < 4; j++)
                sP[(ty * 4 + i) * PSTRIDE + tx * 4 + j] = sacc[i][j];
        __syncthreads();

        if (tid < 64) {
            int r = tid;
            int gq_idx = qt * 64 + r;
            float mx = sM[r];
            for (int j = 0; j < 64; j++) {
                int kk = kt * 64 + j;
                float vv = sP[r * PSTRIDE + j];
                bool valid = (kk <= gq_idx) && (mrow[kk] > 0.f);
                vv = valid ? vv : -1e30f;
                sP[r * PSTRIDE + j] = vv;
                mx = fmaxf(mx, vv);
            }
            float m_new = mx;
            float corr = expf(sM[r] - m_new);
            float sum = 0.f;
            for (int j = 0; j < 64; j++) {
                float p = expf(sP[r * PSTRIDE + j] - m_new);
                sP[r * PSTRIDE + j] = p;
                sum += p;
            }
            sL[r] = sL[r] * corr + sum;
            sM[r] = m_new;
            sC[r] = corr;
        }
        __syncthreads();

        float cc[4];
#pragma unroll
        for (int i = 0; i < 4; i++) cc[i] = sC[ty * 4 + i];
#pragma unroll
        for (int i = 0; i < 4; i++)
#pragma unroll
            for (int j = 0; j < 8; j++) acc[i][j] *= cc[i];

#pragma unroll 8
        for (int k = 0; k < 64; k++) {
            float a[4];
#pragma unroll
            for (int i = 0; i < 4; i++) a[i] = sP[(ty * 4 + i) * PSTRIDE + k];
            float4 v0 = *(const float4*)(sV + k * QSTRIDE + tx * 8);
            float4 v1 = *(const float4*)(sV + k * QSTRIDE + tx * 8 + 4);
#pragma unroll
            for (int i = 0; i < 4; i++) {
                acc[i][0] = fmaf(a[i], v0.x, acc[i][0]);
                acc[i][1] = fmaf(a[i], v0.y, acc[i][1]);
                acc[i][2] = fmaf(a[i], v0.z, acc[i][2]);
                acc[i][3] = fmaf(a[i], v0.w, acc[i][3]);
                acc[i][4] = fmaf(a[i], v1.x, acc[i][4]);
                acc[i][5] = fmaf(a[i], v1.y, acc[i][5]);
                acc[i][6] = fmaf(a[i], v1.z, acc[i][6]);
                acc[i][7] = fmaf(a[i], v1.w, acc[i][7]);
            }
        }
    }

#pragma unroll
    for (int i = 0; i < 4; i++) {
        float invl = 1.f / sL[ty * 4 + i];
        float* orow = O + (size_t)(b * S_ + qt * 64 + ty * 4 + i) * D_ + h * HD + tx * 8;
        *(float4*)(orow)     = make_float4(acc[i][0] * invl, acc[i][1] * invl,
                                           acc[i][2] * invl, acc[i][3] * invl);
        *(float4*)(orow + 4) = make_float4(acc[i][4] * invl, acc[i][5] * invl,
                                           acc[i][6] * invl, acc[i][7] * invl);
    }
}

// =====================  launch  =============================================
extern "C" void kernel_launch(void* const* d_in, const int* in_sizes, int n_in,
                              void* d_out, int out_size)
{
    const float* x     = (const float*)d_in[0];
    const float* amask = (const float*)d_in[1];
    const int*   pos   = (const int*)  d_in[2];
    const float* wq    = (const float*)d_in[3];
    const float* wk    = (const float*)d_in[4];
    const float* wv    = (const float*)d_in[5];
    const float* wo    = (const float*)d_in[6];
    float* out = (float*)d_out;

    float *q, *k, *v, *ao;
    __nv_bfloat16 *abf, *wbf;
    cudaGetSymbolAddress((void**)&q,   g_q);
    cudaGetSymbolAddress((void**)&k,   g_k);
    cudaGetSymbolAddress((void**)&v,   g_v);
    cudaGetSymbolAddress((void**)&ao,  g_ao);
    cudaGetSymbolAddress((void**)&abf, g_Abf);
    cudaGetSymbolAddress((void**)&wbf, g_Wbf);

    __nv_bfloat16* wq_bf = wbf;
    __nv_bfloat16* wk_bf = wq_bf + (size_t)D_ * K3;
    __nv_bfloat16* wv_bf = wk_bf + (size_t)KVDIM * K3;
    __nv_bfloat16* wo_bf = wv_bf + (size_t)KVDIM * K3;

    cudaFuncSetAttribute(gemm_bf16_kernel, cudaFuncAttributeMaxDynamicSharedMemorySize, GEMM_SMEM);
    cudaFuncSetAttribute(flash_kernel, cudaFuncAttributeMaxDynamicSharedMemorySize, FLASH_SMEM_BYTES);

    // RoPE tables
    rope_table_kernel<<<(4096 * 64 + 255) / 256, 256>>>();

    // Split-precision conversions
    convert_a_kernel<<<(MTOK * D_ / 4) / 256, 256>>>(x, abf);
    convert_w_kernel<<<dim3(D_ / 32,    D_ / 32), dim3(32, 8)>>>(wq, wq_bf, D_);
    convert_w_kernel<<<dim3(KVDIM / 32, D_ / 32), dim3(32, 8)>>>(wk, wk_bf, KVDIM);
    convert_w_kernel<<<dim3(KVDIM / 32, D_ / 32), dim3(32, 8)>>>(wv, wv_bf, KVDIM);
    convert_w_kernel<<<dim3(D_ / 32,    D_ / 32), dim3(32, 8)>>>(wo, wo_bf, D_);

    // QKV projections (mma.sync bf16)
    gemm_bf16_kernel<<<dim3(D_ / 128,    MTOK / 128), 256, GEMM_SMEM>>>(abf, wq_bf, q, D_);
    gemm_bf16_kernel<<<dim3(KVDIM / 128, MTOK / 128), 256, GEMM_SMEM>>>(abf, wk_bf, k, KVDIM);
    gemm_bf16_kernel<<<dim3(KVDIM / 128, MTOK / 128), 256, GEMM_SMEM>>>(abf, wv_bf, v, KVDIM);

    // RoPE
    rope_apply_kernel<<<(MTOK * NH  * 64 + 255) / 256, 256>>>(q, pos, NH);
    rope_apply_kernel<<<(MTOK * NKV * 64 + 255) / 256, 256>>>(k, pos, NKV);

    // Attention
    flash_kernel<<<dim3(S_ / 64, NH, B_), 256, FLASH_SMEM_BYTES>>>(q, k, v, amask, ao);

    // Output projection
    convert_a_kernel<<<(MTOK * D_ / 4) / 256, 256>>>(ao, abf);
    gemm_bf16_kernel<<<dim3(D_ / 128, MTOK / 128), 256, GEMM_SMEM>>>(abf, wo_bf, out, D_);
}

// round 5
// speedup vs baseline: 3.7941x; 2.1279x over previous
#include <cuda_runtime.h>
#include <cuda_bf16.h>
#include <cstdint>
#include <math.h>

// Problem constants
#define B_    2
#define S_    2048
#define D_    4096
#define NH    32
#define NKV   8
#define HD    128
#define MTOK  (B_*S_)          // 4096 tokens
#define KVDIM (NKV*HD)         // 1024
#define K3    12288            // 3 * 4096 (split-precision stacked K)
#define ROPE_THETA 500000.0

// -------------------- scratch (device globals; no allocs allowed) -----------
__device__ float g_q [(size_t)MTOK * D_];
__device__ float g_k [(size_t)MTOK * KVDIM];
__device__ float g_v [(size_t)MTOK * KVDIM];
__device__ float g_ao[(size_t)MTOK * D_];
__device__ float g_cos[4096 * 64];
__device__ float g_sin[4096 * 64];
__device__ __nv_bfloat16 g_Abf[(size_t)MTOK * K3];
__device__ __nv_bfloat16 g_Wbf[(size_t)(D_ + KVDIM + KVDIM + D_) * K3];

// =====================  PTX helpers (baseline ISA only)  ====================
__device__ __forceinline__ uint32_t smem_u32(const void* p) {
    uint32_t a;
    asm("{ .reg .u64 t; cvta.to.shared.u64 t, %1; cvt.u32.u64 %0, t; }" : "=r"(a) : "l"(p));
    return a;
}
__device__ __forceinline__ void cp_async16(uint32_t s, const void* g) {
    asm volatile("cp.async.cg.shared.global [%0], [%1], 16;" :: "r"(s), "l"(g));
}
__device__ __forceinline__ void cp_commit() {
    asm volatile("cp.async.commit_group;" ::: "memory");
}
template<int N_> __device__ __forceinline__ void cp_wait() {
    asm volatile("cp.async.wait_group %0;" :: "n"(N_) : "memory");
}
__device__ __forceinline__ void ldmatrix_x4(uint32_t* r, uint32_t addr) {
    asm volatile("ldmatrix.sync.aligned.m8n8.x4.shared.b16 {%0,%1,%2,%3}, [%4];"
                 : "=r"(r[0]), "=r"(r[1]), "=r"(r[2]), "=r"(r[3]) : "r"(addr));
}
__device__ __forceinline__ void ldmatrix_x4_trans(uint32_t* r, uint32_t addr) {
    asm volatile("ldmatrix.sync.aligned.m8n8.x4.trans.shared.b16 {%0,%1,%2,%3}, [%4];"
                 : "=r"(r[0]), "=r"(r[1]), "=r"(r[2]), "=r"(r[3]) : "r"(addr));
}
__device__ __forceinline__ void ldmatrix_x2(uint32_t* r, uint32_t addr) {
    asm volatile("ldmatrix.sync.aligned.m8n8.x2.shared.b16 {%0,%1}, [%2];"
                 : "=r"(r[0]), "=r"(r[1]) : "r"(addr));
}
__device__ __forceinline__ void mma_16816(float* d, const uint32_t* a, const uint32_t* b) {
    asm volatile(
        "mma.sync.aligned.m16n8k16.row.col.f32.bf16.bf16.f32 "
        "{%0,%1,%2,%3}, {%4,%5,%6,%7}, {%8,%9}, {%0,%1,%2,%3};"
        : "+f"(d[0]), "+f"(d[1]), "+f"(d[2]), "+f"(d[3])
        : "r"(a[0]), "r"(a[1]), "r"(a[2]), "r"(a[3]), "r"(b[0]), "r"(b[1]));
}
__device__ __forceinline__ uint32_t pk_bf16x2(float lo, float hi) {
    uint32_t d;
    asm("cvt.rn.bf16x2.f32 %0, %1, %2;" : "=r"(d) : "f"(hi), "f"(lo));
    return d;
}
__device__ __forceinline__ float2 unpk_bf16x2(uint32_t u) {
    float2 r;
    r.x = __uint_as_float(u << 16);
    r.y = __uint_as_float(u & 0xffff0000u);
    return r;
}

// =====================  conversion kernels  =================================
__global__ __launch_bounds__(256) void convert_a_kernel(const float* __restrict__ X,
                                                        __nv_bfloat16* __restrict__ Y) {
    int i = blockIdx.x * blockDim.x + threadIdx.x;
    int row = i >> 10;
    int col = (i & 1023) << 2;
    float4 v = ((const float4*)X)[i];
    __nv_bfloat16 hx = __float2bfloat16_rn(v.x);
    __nv_bfloat16 hy = __float2bfloat16_rn(v.y);
    __nv_bfloat16 hz = __float2bfloat16_rn(v.z);
    __nv_bfloat16 hw = __float2bfloat16_rn(v.w);
    __nv_bfloat16 lx = __float2bfloat16_rn(v.x - __bfloat162float(hx));
    __nv_bfloat16 ly = __float2bfloat16_rn(v.y - __bfloat162float(hy));
    __nv_bfloat16 lz = __float2bfloat16_rn(v.z - __bfloat162float(hz));
    __nv_bfloat16 lw = __float2bfloat16_rn(v.w - __bfloat162float(hw));
    size_t base = (size_t)row * K3 + col;
    __nv_bfloat162 h01 = __halves2bfloat162(hx, hy);
    __nv_bfloat162 h23 = __halves2bfloat162(hz, hw);
    __nv_bfloat162 l01 = __halves2bfloat162(lx, ly);
    __nv_bfloat162 l23 = __halves2bfloat162(lz, lw);
    ((__nv_bfloat162*)(Y + base))[0] = h01;
    ((__nv_bfloat162*)(Y + base))[1] = h23;
    ((__nv_bfloat162*)(Y + base + 4096))[0] = l01;
    ((__nv_bfloat162*)(Y + base + 4096))[1] = l23;
    ((__nv_bfloat162*)(Y + base + 8192))[0] = h01;
    ((__nv_bfloat162*)(Y + base + 8192))[1] = h23;
}

__global__ __launch_bounds__(256) void convert_w_kernel(const float* __restrict__ W,
                                                        __nv_bfloat16* __restrict__ Y, int N) {
    __shared__ float t[32][33];
    int n0 = blockIdx.x * 32;
    int k0 = blockIdx.y * 32;
    int tx = threadIdx.x;
    int ty = threadIdx.y;
#pragma unroll
    for (int i = 0; i < 4; i++)
        t[ty + 8 * i][tx] = W[(size_t)(k0 + ty + 8 * i) * N + n0 + tx];
    __syncthreads();
#pragma unroll
    for (int i = 0; i < 4; i++) {
        int r = ty + 8 * i;
        float v = t[tx][r];
        __nv_bfloat16 hi = __float2bfloat16_rn(v);
        __nv_bfloat16 lo = __float2bfloat16_rn(v - __bfloat162float(hi));
        size_t base = (size_t)(n0 + r) * K3 + k0 + tx;
        Y[base] = hi;
        Y[base + 4096] = hi;
        Y[base + 8192] = lo;
    }
}

// elementwise split: X fp32 -> (H, L) bf16 with optional pre-scale
__global__ __launch_bounds__(256) void split_kernel(const float* __restrict__ X,
                                                    __nv_bfloat16* __restrict__ H,
                                                    __nv_bfloat16* __restrict__ L,
                                                    float scale, int n4) {
    int i = blockIdx.x * blockDim.x + threadIdx.x;
    if (i >= n4) return;
    float4 v = ((const float4*)X)[i];
    v.x *= scale; v.y *= scale; v.z *= scale; v.w *= scale;
    __nv_bfloat16 hx = __float2bfloat16_rn(v.x);
    __nv_bfloat16 hy = __float2bfloat16_rn(v.y);
    __nv_bfloat16 hz = __float2bfloat16_rn(v.z);
    __nv_bfloat16 hw = __float2bfloat16_rn(v.w);
    __nv_bfloat16 lx = __float2bfloat16_rn(v.x - __bfloat162float(hx));
    __nv_bfloat16 ly = __float2bfloat16_rn(v.y - __bfloat162float(hy));
    __nv_bfloat16 lz = __float2bfloat16_rn(v.z - __bfloat162float(hz));
    __nv_bfloat16 lw = __float2bfloat16_rn(v.w - __bfloat162float(hw));
    ((__nv_bfloat162*)H)[2 * i]     = __halves2bfloat162(hx, hy);
    ((__nv_bfloat162*)H)[2 * i + 1] = __halves2bfloat162(hz, hw);
    ((__nv_bfloat162*)L)[2 * i]     = __halves2bfloat162(lx, ly);
    ((__nv_bfloat162*)L)[2 * i + 1] = __halves2bfloat162(lz, lw);
}

// =====================  mma.sync bf16 GEMM  =================================
#define BKK 64
#define NST 3
#define STAGE_BYTES 32768
#define GEMM_SMEM (NST * STAGE_BYTES)

__device__ __forceinline__ void gemm_load_stage(
    const __nv_bfloat16* __restrict__ A, const __nv_bfloat16* __restrict__ Bt,
    int m0, int n0, int it, uint32_t sA, int tid)
{
    int k0 = it * BKK;
    uint32_t sB = sA + 16384u;
#pragma unroll
    for (int u = 0; u < 4; u++) {
        int f = u * 256 + tid;
        int r = f >> 3;
        int c = f & 7;
        uint32_t sw = (uint32_t)(c ^ (r & 7));
        cp_async16(sA + (uint32_t)r * 128u + sw * 16u,
                   A + (size_t)(m0 + r) * K3 + k0 + c * 8);
    }
#pragma unroll
    for (int u = 0; u < 4; u++) {
        int f = u * 256 + tid;
        int r = f >> 3;
        int c = f & 7;
        uint32_t sw = (uint32_t)(c ^ (r & 7));
        cp_async16(sB + (uint32_t)r * 128u + sw * 16u,
                   Bt + (size_t)(n0 + r) * K3 + k0 + c * 8);
    }
    cp_commit();
}

__global__ __launch_bounds__(256) void gemm_bf16_kernel(
    const __nv_bfloat16* __restrict__ A, const __nv_bfloat16* __restrict__ Bt,
    float* __restrict__ C, int N)
{
    extern __shared__ __align__(1024) char gsm[];
    const uint32_t sbase = smem_u32(gsm);
    const int tid  = threadIdx.x;
    const int wid  = tid >> 5;
    const int lane = tid & 31;

    const int m0 = blockIdx.y * 128;
    const int n0 = blockIdx.x * 128;
    const int wm = (wid >> 2) * 64;
    const int wn = (wid & 3) * 32;

    float acc[4][4][4];
#pragma unroll
    for (int i = 0; i < 4; i++)
#pragma unroll
        for (int j = 0; j < 4; j++)
#pragma unroll
            for (int e = 0; e < 4; e++) acc[i][j][e] = 0.f;

    const int iters = K3 / BKK;
    gemm_load_stage(A, Bt, m0, n0, 0, sbase + 0u * STAGE_BYTES, tid);
    gemm_load_stage(A, Bt, m0, n0, 1, sbase + 1u * STAGE_BYTES, tid);

    const int a_row_in16 = ((lane >> 3) & 1) * 8 + (lane & 7);
    const int a_cadd     = lane >> 4;
    const int b_row_in8  = lane & 7;
    const int b_cadd     = (lane >> 3) & 1;

    for (int it = 0; it < iters; it++) {
        cp_wait<1>();
        __syncthreads();
        if (it + 2 < iters)
            gemm_load_stage(A, Bt, m0, n0, it + 2,
                            sbase + (uint32_t)((it + 2) % NST) * STAGE_BYTES, tid);

        uint32_t sA = sbase + (uint32_t)(it % NST) * STAGE_BYTES;
        uint32_t sB = sA + 16384u;

#pragma unroll
        for (int ks = 0; ks < 4; ks++) {
            int c0 = ks * 2;
            uint32_t afr[4][4];
#pragma unroll
            for (int im = 0; im < 4; im++) {
                int r  = wm + im * 16 + a_row_in16;
                int cc = c0 + a_cadd;
                uint32_t addr = sA + (uint32_t)r * 128u + (uint32_t)((cc ^ (r & 7)) * 16);
                ldmatrix_x4(afr[im], addr);
            }
            uint32_t bfr[4][2];
#pragma unroll
            for (int jn = 0; jn < 4; jn++) {
                int r  = wn + jn * 8 + b_row_in8;
                int cc = c0 + b_cadd;
                uint32_t addr = sB + (uint32_t)r * 128u + (uint32_t)((cc ^ (r & 7)) * 16);
                ldmatrix_x2(bfr[jn], addr);
            }
#pragma unroll
            for (int im = 0; im < 4; im++)
#pragma unroll
                for (int jn = 0; jn < 4; jn++)
                    mma_16816(acc[im][jn], afr[im], bfr[jn]);
        }
    }

    const int tg = lane >> 2;
    const int tc = lane & 3;
#pragma unroll
    for (int im = 0; im < 4; im++) {
#pragma unroll
        for (int jn = 0; jn < 4; jn++) {
            int row = m0 + wm + im * 16 + tg;
            int col = n0 + wn + jn * 8 + tc * 2;
            float2 v0 = make_float2(acc[im][jn][0], acc[im][jn][1]);
            float2 v1 = make_float2(acc[im][jn][2], acc[im][jn][3]);
            *(float2*)(C + (size_t)row * N + col) = v0;
            *(float2*)(C + (size_t)(row + 8) * N + col) = v1;
        }
    }
}

// =====================  RoPE  ===============================================
__global__ void rope_table_kernel() {
    int idx = blockIdx.x * blockDim.x + threadIdx.x;
    if (idx >= 4096 * 64) return;
    int p = idx >> 6;
    int i = idx & 63;
    double inv = exp(-((double)(2 * i) / (double)HD) * log(ROPE_THETA));
    double ang = (double)p * inv;
    g_cos[idx] = (float)cos(ang);
    g_sin[idx] = (float)sin(ang);
}

__global__ void rope_apply_kernel(float* __restrict__ x, const int* __restrict__ pos,
                                  int nheads) {
    int idx = blockIdx.x * blockDim.x + threadIdx.x;
    int total = MTOK * nheads * 64;
    if (idx >= total) return;
    int i = idx & 63;
    int rem = idx >> 6;
    int h = rem % nheads;
    int t = rem / nheads;
    int p = pos[t];
    float c = g_cos[p * 64 + i];
    float s = g_sin[p * 64 + i];
    size_t off = (size_t)t * (nheads * HD) + h * HD + 2 * i;
    float a = x[off];
    float b = x[off + 1];
    x[off]     = a * c - b * s;
    x[off + 1] = a * s + b * c;
}

// =====================  Flash attention (mma.sync, split bf16)  =============
// CTA: 64 q-rows x 64 kv, 4 warps, each warp 16 q-rows.
// smem: Qh,Ql,Kh,Kl,Vh,Vl tiles 64x128 bf16 (16KB each, swizzled) + 64-float mask.
#define FL_SMEM (6 * 16384 + 256)

__global__ __launch_bounds__(128) void flash_mma_kernel(
    const __nv_bfloat16* __restrict__ Qh, const __nv_bfloat16* __restrict__ Ql,
    const __nv_bfloat16* __restrict__ Kh, const __nv_bfloat16* __restrict__ Kl,
    const __nv_bfloat16* __restrict__ Vh, const __nv_bfloat16* __restrict__ Vl,
    const float* __restrict__ amask, float* __restrict__ O)
{
    extern __shared__ __align__(1024) char fsm[];
    const uint32_t sb = smem_u32(fsm);
    float* sMask = (float*)(fsm + 98304);

    const int tid  = threadIdx.x;
    const int warp = tid >> 5;
    const int lane = tid & 31;
    const int tg   = lane >> 2;
    const int tc   = lane & 3;
    const int qt   = (S_ / 64 - 1) - blockIdx.x;   // long tiles first
    const int h    = blockIdx.y;
    const int b    = blockIdx.z;
    const int kvh  = h >> 2;

    // ---- load Q tiles (hi, lo) ----
    {
        const __nv_bfloat16* qs[2] = {Qh, Ql};
#pragma unroll
        for (int t = 0; t < 16; t++) {
            int f = t * 128 + tid;
            int tile = t >> 3;
            int ft = f & 1023;
            int r = ft >> 4, c = ft & 15;
            uint32_t dst = sb + (uint32_t)tile * 16384u + (uint32_t)r * 256u +
                           (uint32_t)((c ^ (r & 7)) * 16);
            cp_async16(dst, qs[tile] + (size_t)(b * S_ + qt * 64 + r) * D_ + h * HD + c * 8);
        }
        cp_commit();
    }

    float acc_o[16][4];
#pragma unroll
    for (int i = 0; i < 16; i++)
#pragma unroll
        for (int e = 0; e < 4; e++) acc_o[i][e] = 0.f;
    float m0 = -INFINITY, m1 = -INFINITY, l0 = 0.f, l1 = 0.f;

    // per-lane ldmatrix addressing components
    const int a_r16  = ((lane >> 3) & 1) * 8 + (lane & 7);   // A (Q) rows
    const int a_cs   = lane >> 4;
    const int b_nsel = lane >> 4;                            // K rows: which nj of pair
    const int b_row8 = lane & 7;
    const int b_cs   = (lane >> 3) & 1;
    const int v_half = (lane >> 3) & 1;                      // V(trans) rows
    const int v_sel  = lane >> 4;
    const int v_row7 = lane & 7;

    for (int kt = 0; kt <= qt; kt++) {
        if (kt) __syncthreads();     // protect smem before overwrite
        // ---- load K/V tiles (hi, lo) ----
        {
            const __nv_bfloat16* kvs[4] = {Kh, Kl, Vh, Vl};
#pragma unroll
            for (int t = 0; t < 32; t++) {
                int f = t * 128 + tid;
                int tile = t >> 3;
                int ft = f & 1023;
                int r = ft >> 4, c = ft & 15;
                uint32_t dst = sb + 32768u + (uint32_t)tile * 16384u + (uint32_t)r * 256u +
                               (uint32_t)((c ^ (r & 7)) * 16);
                cp_async16(dst, kvs[tile] + (size_t)(b * S_ + kt * 64 + r) * KVDIM + kvh * HD + c * 8);
            }
            cp_commit();
        }
        if (tid < 64) sMask[tid] = amask[b * S_ + kt * 64 + tid];
        cp_wait<0>();
        __syncthreads();

        // ---- S = Q K^T (split: qh*kh + ql*kh + qh*kl) ----
        float accs[8][4];
#pragma unroll
        for (int nj = 0; nj < 8; nj++)
#pragma unroll
            for (int e = 0; e < 4; e++) accs[nj][e] = 0.f;

#pragma unroll
        for (int kc = 0; kc < 8; kc++) {
            uint32_t qh4[4], ql4[4];
            {
                int r = warp * 16 + a_r16;
                int cc = kc * 2 + a_cs;
                uint32_t off = (uint32_t)r * 256u + (uint32_t)((cc ^ (r & 7)) * 16);
                ldmatrix_x4(qh4, sb + off);
                ldmatrix_x4(ql4, sb + 16384u + off);
            }
#pragma unroll
            for (int njp = 0; njp < 4; njp++) {
                uint32_t kh4[4], kl4[4];
                int r = (njp * 2 + b_nsel) * 8 + b_row8;
                int cc = kc * 2 + b_cs;
                uint32_t off = (uint32_t)r * 256u + (uint32_t)((cc ^ (r & 7)) * 16);
                ldmatrix_x4(kh4, sb + 32768u + off);
                ldmatrix_x4(kl4, sb + 49152u + off);
                mma_16816(accs[2 * njp],     qh4, kh4);
                mma_16816(accs[2 * njp],     ql4, kh4);
                mma_16816(accs[2 * njp],     qh4, kl4);
                mma_16816(accs[2 * njp + 1], qh4, kh4 + 2);
                mma_16816(accs[2 * njp + 1], ql4, kh4 + 2);
                mma_16816(accs[2 * njp + 1], qh4, kl4 + 2);
            }
        }

        // ---- mask + online softmax ----
        const bool diag = (kt == qt);
        float mx0 = -INFINITY, mx1 = -INFINITY;
#pragma unroll
        for (int nj = 0; nj < 8; nj++) {
#pragma unroll
            for (int e = 0; e < 4; e++) {
                int kvl = nj * 8 + 2 * tc + (e & 1);
                bool valid = sMask[kvl] > 0.f;
                if (diag) {
                    int qloc = warp * 16 + tg + ((e >> 1) ? 8 : 0);
                    valid = valid && (kvl <= qloc);
                }
                float s = valid ? accs[nj][e] : -1e30f;
                accs[nj][e] = s;
                if (e < 2) mx0 = fmaxf(mx0, s); else mx1 = fmaxf(mx1, s);
            }
        }
        mx0 = fmaxf(mx0, __shfl_xor_sync(0xffffffffu, mx0, 1));
        mx0 = fmaxf(mx0, __shfl_xor_sync(0xffffffffu, mx0, 2));
        mx1 = fmaxf(mx1, __shfl_xor_sync(0xffffffffu, mx1, 1));
        mx1 = fmaxf(mx1, __shfl_xor_sync(0xffffffffu, mx1, 2));

        float mn0 = fmaxf(m0, mx0), mn1 = fmaxf(m1, mx1);
        float cr0 = __expf(m0 - mn0), cr1 = __expf(m1 - mn1);
        m0 = mn0; m1 = mn1;

        float s0 = 0.f, s1 = 0.f;
#pragma unroll
        for (int nj = 0; nj < 8; nj++) {
#pragma unroll
            for (int e = 0; e < 4; e++) {
                float p = __expf(accs[nj][e] - ((e < 2) ? m0 : m1));
                accs[nj][e] = p;
                if (e < 2) s0 += p; else s1 += p;
            }
        }
        s0 += __shfl_xor_sync(0xffffffffu, s0, 1);
        s0 += __shfl_xor_sync(0xffffffffu, s0, 2);
        s1 += __shfl_xor_sync(0xffffffffu, s1, 1);
        s1 += __shfl_xor_sync(0xffffffffu, s1, 2);
        l0 = l0 * cr0 + s0;
        l1 = l1 * cr1 + s1;

#pragma unroll
        for (int nd = 0; nd < 16; nd++) {
            acc_o[nd][0] *= cr0; acc_o[nd][1] *= cr0;
            acc_o[nd][2] *= cr1; acc_o[nd][3] *= cr1;
        }

        // ---- O += P V (split: ph*vh + pl*vh + ph*vl) ----
#pragma unroll
        for (int kc2 = 0; kc2 < 4; kc2++) {
            float* p0 = accs[2 * kc2];
            float* p1 = accs[2 * kc2 + 1];
            uint32_t ah[4], al[4];
            ah[0] = pk_bf16x2(p0[0], p0[1]);
            ah[1] = pk_bf16x2(p0[2], p0[3]);
            ah[2] = pk_bf16x2(p1[0], p1[1]);
            ah[3] = pk_bf16x2(p1[2], p1[3]);
            {
                float2 f;
                f = unpk_bf16x2(ah[0]); al[0] = pk_bf16x2(p0[0] - f.x, p0[1] - f.y);
                f = unpk_bf16x2(ah[1]); al[1] = pk_bf16x2(p0[2] - f.x, p0[3] - f.y);
                f = unpk_bf16x2(ah[2]); al[2] = pk_bf16x2(p1[0] - f.x, p1[1] - f.y);
                f = unpk_bf16x2(ah[3]); al[3] = pk_bf16x2(p1[2] - f.x, p1[3] - f.y);
            }
            int vr = kc2 * 16 + v_half * 8 + v_row7;
#pragma unroll
            for (int ndp = 0; ndp < 8; ndp++) {
                int chunk = ndp * 2 + v_sel;
                uint32_t off = (uint32_t)vr * 256u + (uint32_t)((chunk ^ (vr & 7)) * 16);
                uint32_t bh4[4], bl4[4];
                ldmatrix_x4_trans(bh4, sb + 65536u + off);
                ldmatrix_x4_trans(bl4, sb + 81920u + off);
                mma_16816(acc_o[2 * ndp],     ah, bh4);
                mma_16816(acc_o[2 * ndp],     al, bh4);
                mma_16816(acc_o[2 * ndp],     ah, bl4);
                mma_16816(acc_o[2 * ndp + 1], ah, bh4 + 2);
                mma_16816(acc_o[2 * ndp + 1], al, bh4 + 2);
                mma_16816(acc_o[2 * ndp + 1], ah, bl4 + 2);
            }
        }
    }

    // ---- normalize + write ----
    float inv0 = 1.f / l0, inv1 = 1.f / l1;
    int row0 = b * S_ + qt * 64 + warp * 16 + tg;
#pragma unroll
    for (int nd = 0; nd < 16; nd++) {
        int col = h * HD + nd * 8 + 2 * tc;
        float2 v0 = make_float2(acc_o[nd][0] * inv0, acc_o[nd][1] * inv0);
        float2 v1 = make_float2(acc_o[nd][2] * inv1, acc_o[nd][3] * inv1);
        *(float2*)(O + (size_t)row0 * D_ + col) = v0;
        *(float2*)(O + (size_t)(row0 + 8) * D_ + col) = v1;
    }
}

// =====================  launch  =============================================
extern "C" void kernel_launch(void* const* d_in, const int* in_sizes, int n_in,
                              void* d_out, int out_size)
{
    const float* x     = (const float*)d_in[0];
    const float* amask = (const float*)d_in[1];
    const int*   pos   = (const int*)  d_in[2];
    const float* wq    = (const float*)d_in[3];
    const float* wk    = (const float*)d_in[4];
    const float* wv    = (const float*)d_in[5];
    const float* wo    = (const float*)d_in[6];
    float* out = (float*)d_out;

    float *q, *k, *v, *ao;
    __nv_bfloat16 *abf, *wbf;
    cudaGetSymbolAddress((void**)&q,   g_q);
    cudaGetSymbolAddress((void**)&k,   g_k);
    cudaGetSymbolAddress((void**)&v,   g_v);
    cudaGetSymbolAddress((void**)&ao,  g_ao);
    cudaGetSymbolAddress((void**)&abf, g_Abf);
    cudaGetSymbolAddress((void**)&wbf, g_Wbf);

    __nv_bfloat16* wq_bf = wbf;
    __nv_bfloat16* wk_bf = wq_bf + (size_t)D_ * K3;
    __nv_bfloat16* wv_bf = wk_bf + (size_t)KVDIM * K3;
    __nv_bfloat16* wo_bf = wv_bf + (size_t)KVDIM * K3;

    // flash split buffers aliased into g_Abf (free between QKV GEMMs and out-proj convert)
    const size_t QSZ = (size_t)MTOK * D_;
    const size_t KSZ = (size_t)MTOK * KVDIM;
    __nv_bfloat16* qh = abf;
    __nv_bfloat16* ql = qh + QSZ;
    __nv_bfloat16* kh = ql + QSZ;
    __nv_bfloat16* kl = kh + KSZ;
    __nv_bfloat16* vh = kl + KSZ;
    __nv_bfloat16* vl = vh + KSZ;

    cudaFuncSetAttribute(gemm_bf16_kernel, cudaFuncAttributeMaxDynamicSharedMemorySize, GEMM_SMEM);
    cudaFuncSetAttribute(flash_mma_kernel, cudaFuncAttributeMaxDynamicSharedMemorySize, FL_SMEM);

    // RoPE tables
    rope_table_kernel<<<(4096 * 64 + 255) / 256, 256>>>();

    // Split-precision conversions for GEMMs
    convert_a_kernel<<<(MTOK * D_ / 4) / 256, 256>>>(x, abf);
    convert_w_kernel<<<dim3(D_ / 32,    D_ / 32), dim3(32, 8)>>>(wq, wq_bf, D_);
    convert_w_kernel<<<dim3(KVDIM / 32, D_ / 32), dim3(32, 8)>>>(wk, wk_bf, KVDIM);
    convert_w_kernel<<<dim3(KVDIM / 32, D_ / 32), dim3(32, 8)>>>(wv, wv_bf, KVDIM);
    convert_w_kernel<<<dim3(D_ / 32,    D_ / 32), dim3(32, 8)>>>(wo, wo_bf, D_);

    // QKV projections (mma.sync bf16)
    gemm_bf16_kernel<<<dim3(D_ / 128,    MTOK / 128), 256, GEMM_SMEM>>>(abf, wq_bf, q, D_);
    gemm_bf16_kernel<<<dim3(KVDIM / 128, MTOK / 128), 256, GEMM_SMEM>>>(abf, wk_bf, k, KVDIM);
    gemm_bf16_kernel<<<dim3(KVDIM / 128, MTOK / 128), 256, GEMM_SMEM>>>(abf, wv_bf, v, KVDIM);

    // RoPE
    rope_apply_kernel<<<(MTOK * NH  * 64 + 255) / 256, 256>>>(q, pos, NH);
    rope_apply_kernel<<<(MTOK * NKV * 64 + 255) / 256, 256>>>(k, pos, NKV);

    // Split Q/K/V for flash (Q pre-scaled by 1/sqrt(HD))
    const float scale = 0.08838834764831845f;
    split_kernel<<<(int)((QSZ / 4 + 255) / 256), 256>>>(q, qh, ql, scale, (int)(QSZ / 4));
    split_kernel<<<(int)((KSZ / 4 + 255) / 256), 256>>>(k, kh, kl, 1.0f, (int)(KSZ / 4));
    split_kernel<<<(int)((KSZ / 4 + 255) / 256), 256>>>(v, vh, vl, 1.0f, (int)(KSZ / 4));

    // Attention (tensor-core flash)
    flash_mma_kernel<<<dim3(S_ / 64, NH, B_), 128, FL_SMEM>>>(qh, ql, kh, kl, vh, vl, amask, ao);

    // Output projection
    convert_a_kernel<<<(MTOK * D_ / 4) / 256, 256>>>(ao, abf);
    gemm_bf16_kernel<<<dim3(D_ / 128, MTOK / 128), 256, GEMM_SMEM>>>(abf, wo_bf, out, D_);
}

// round 6
// speedup vs baseline: 3.8648x; 1.0186x over previous
#include <cuda_runtime.h>
#include <cuda_bf16.h>
#include <cstdint>
#include <math.h>

// Problem constants
#define B_    2
#define S_    2048
#define D_    4096
#define NH    32
#define NKV   8
#define HD    128
#define MTOK  (B_*S_)          // 4096 tokens
#define KVDIM (NKV*HD)         // 1024
#define QKVN  (D_ + 2*KVDIM)   // 6144 fused projection width
#define K2    8192             // 2 * 4096 (hi|lo split storage)
#define ROPE_THETA 500000.0

// -------------------- scratch (device globals; no allocs allowed) -----------
__device__ float g_qkv[(size_t)MTOK * QKVN];   // fused QKV output (row stride 6144)
__device__ float g_ao [(size_t)MTOK * D_];
__device__ float g_cos[2048 * 64];
__device__ float g_sin[2048 * 64];
// A operand (hi|lo, K2) for GEMMs; later aliased as flash split buffers
__device__ __nv_bfloat16 g_Abf[(size_t)MTOK * 12288];
// weights: [qkv rows 0..6144) | wo rows 6144..10240), row stride K2
__device__ __nv_bfloat16 g_Wbf[(size_t)10240 * K2];

// =====================  PTX helpers (baseline ISA only)  ====================
__device__ __forceinline__ uint32_t smem_u32(const void* p) {
    uint32_t a;
    asm("{ .reg .u64 t; cvta.to.shared.u64 t, %1; cvt.u32.u64 %0, t; }" : "=r"(a) : "l"(p));
    return a;
}
__device__ __forceinline__ void cp_async16(uint32_t s, const void* g) {
    asm volatile("cp.async.cg.shared.global [%0], [%1], 16;" :: "r"(s), "l"(g));
}
__device__ __forceinline__ void cp_commit() {
    asm volatile("cp.async.commit_group;" ::: "memory");
}
template<int N_> __device__ __forceinline__ void cp_wait() {
    asm volatile("cp.async.wait_group %0;" :: "n"(N_) : "memory");
}
__device__ __forceinline__ void ldmatrix_x4(uint32_t* r, uint32_t addr) {
    asm volatile("ldmatrix.sync.aligned.m8n8.x4.shared.b16 {%0,%1,%2,%3}, [%4];"
                 : "=r"(r[0]), "=r"(r[1]), "=r"(r[2]), "=r"(r[3]) : "r"(addr));
}
__device__ __forceinline__ void ldmatrix_x4_trans(uint32_t* r, uint32_t addr) {
    asm volatile("ldmatrix.sync.aligned.m8n8.x4.trans.shared.b16 {%0,%1,%2,%3}, [%4];"
                 : "=r"(r[0]), "=r"(r[1]), "=r"(r[2]), "=r"(r[3]) : "r"(addr));
}
__device__ __forceinline__ void ldmatrix_x2(uint32_t* r, uint32_t addr) {
    asm volatile("ldmatrix.sync.aligned.m8n8.x2.shared.b16 {%0,%1}, [%2];"
                 : "=r"(r[0]), "=r"(r[1]) : "r"(addr));
}
__device__ __forceinline__ void mma_16816(float* d, const uint32_t* a, const uint32_t* b) {
    asm volatile(
        "mma.sync.aligned.m16n8k16.row.col.f32.bf16.bf16.f32 "
        "{%0,%1,%2,%3}, {%4,%5,%6,%7}, {%8,%9}, {%0,%1,%2,%3};"
        : "+f"(d[0]), "+f"(d[1]), "+f"(d[2]), "+f"(d[3])
        : "r"(a[0]), "r"(a[1]), "r"(a[2]), "r"(a[3]), "r"(b[0]), "r"(b[1]));
}
__device__ __forceinline__ uint32_t pk_bf16x2(float lo, float hi) {
    uint32_t d;
    asm("cvt.rn.bf16x2.f32 %0, %1, %2;" : "=r"(d) : "f"(hi), "f"(lo));
    return d;
}
__device__ __forceinline__ float2 unpk_bf16x2(uint32_t u) {
    float2 r;
    r.x = __uint_as_float(u << 16);
    r.y = __uint_as_float(u & 0xffff0000u);
    return r;
}

// =====================  conversion kernels  =================================
// X[4096][4096] fp32 (compact) -> Y[4096][K2] bf16: [0,4096)=hi, [4096,8192)=lo
__global__ __launch_bounds__(256) void convert_a_kernel(const float* __restrict__ X,
                                                        __nv_bfloat16* __restrict__ Y) {
    int i = blockIdx.x * blockDim.x + threadIdx.x;
    int row = i >> 10;
    int col = (i & 1023) << 2;
    float4 v = ((const float4*)X)[i];
    __nv_bfloat16 hx = __float2bfloat16_rn(v.x);
    __nv_bfloat16 hy = __float2bfloat16_rn(v.y);
    __nv_bfloat16 hz = __float2bfloat16_rn(v.z);
    __nv_bfloat16 hw = __float2bfloat16_rn(v.w);
    __nv_bfloat16 lx = __float2bfloat16_rn(v.x - __bfloat162float(hx));
    __nv_bfloat16 ly = __float2bfloat16_rn(v.y - __bfloat162float(hy));
    __nv_bfloat16 lz = __float2bfloat16_rn(v.z - __bfloat162float(hz));
    __nv_bfloat16 lw = __float2bfloat16_rn(v.w - __bfloat162float(hw));
    size_t base = (size_t)row * K2 + col;
    ((__nv_bfloat162*)(Y + base))[0] = __halves2bfloat162(hx, hy);
    ((__nv_bfloat162*)(Y + base))[1] = __halves2bfloat162(hz, hw);
    ((__nv_bfloat162*)(Y + base + 4096))[0] = __halves2bfloat162(lx, ly);
    ((__nv_bfloat162*)(Y + base + 4096))[1] = __halves2bfloat162(lz, lw);
}

// W[K=4096][N] fp32 -> Y[N][K2] bf16 transposed: [0,4096)=hi, [4096,8192)=lo
__global__ __launch_bounds__(256) void convert_w_kernel(const float* __restrict__ W,
                                                        __nv_bfloat16* __restrict__ Y, int N) {
    __shared__ float t[32][33];
    int n0 = blockIdx.x * 32;
    int k0 = blockIdx.y * 32;
    int tx = threadIdx.x;
    int ty = threadIdx.y;
#pragma unroll
    for (int i = 0; i < 4; i++)
        t[ty + 8 * i][tx] = W[(size_t)(k0 + ty + 8 * i) * N + n0 + tx];
    __syncthreads();
#pragma unroll
    for (int i = 0; i < 4; i++) {
        int r = ty + 8 * i;
        float v = t[tx][r];
        __nv_bfloat16 hi = __float2bfloat16_rn(v);
        __nv_bfloat16 lo = __float2bfloat16_rn(v - __bfloat162float(hi));
        size_t base = (size_t)(n0 + r) * K2 + k0 + tx;
        Y[base] = hi;
        Y[base + 4096] = lo;
    }
}

// fused rope + scale + split: X (strided fp32) -> compact (H, L) bf16
__global__ __launch_bounds__(256) void split_rope_kernel(
    const float* __restrict__ X, __nv_bfloat16* __restrict__ H,
    __nv_bfloat16* __restrict__ L, const int* __restrict__ pos,
    float scale, int rl_shift, int srcStride, int do_rope)
{
    int i = blockIdx.x * blockDim.x + threadIdx.x;
    int row = i >> rl_shift;
    int c4 = (i & ((1 << rl_shift) - 1)) << 2;
    float4 v = *(const float4*)(X + (size_t)row * srcStride + c4);
    if (do_rope) {
        int p = pos[row];
        int i0 = (c4 & 127) >> 1;
        float c0 = g_cos[p * 64 + i0],     s0 = g_sin[p * 64 + i0];
        float c1 = g_cos[p * 64 + i0 + 1], s1 = g_sin[p * 64 + i0 + 1];
        float ax = v.x, bx = v.y, az = v.z, bw = v.w;
        v.x = ax * c0 - bx * s0;
        v.y = ax * s0 + bx * c0;
        v.z = az * c1 - bw * s1;
        v.w = az * s1 + bw * c1;
    }
    v.x *= scale; v.y *= scale; v.z *= scale; v.w *= scale;
    __nv_bfloat16 hx = __float2bfloat16_rn(v.x);
    __nv_bfloat16 hy = __float2bfloat16_rn(v.y);
    __nv_bfloat16 hz = __float2bfloat16_rn(v.z);
    __nv_bfloat16 hw = __float2bfloat16_rn(v.w);
    __nv_bfloat16 lx = __float2bfloat16_rn(v.x - __bfloat162float(hx));
    __nv_bfloat16 ly = __float2bfloat16_rn(v.y - __bfloat162float(hy));
    __nv_bfloat16 lz = __float2bfloat16_rn(v.z - __bfloat162float(hz));
    __nv_bfloat16 lw = __float2bfloat16_rn(v.w - __bfloat162float(hw));
    size_t base = ((size_t)row << (rl_shift + 2)) + c4;
    ((__nv_bfloat162*)(H + base))[0] = __halves2bfloat162(hx, hy);
    ((__nv_bfloat162*)(H + base))[1] = __halves2bfloat162(hz, hw);
    ((__nv_bfloat162*)(L + base))[0] = __halves2bfloat162(lx, ly);
    ((__nv_bfloat162*)(L + base))[1] = __halves2bfloat162(lz, lw);
}

// =====================  mma.sync bf16 GEMM (3-term split)  ==================
#define BKK 64
#define NST 3
#define STAGE_BYTES 32768
#define GEMM_SMEM (NST * STAGE_BYTES)

__device__ __forceinline__ int aoff_of(int it) { return ((it >> 6) == 1) ? 4096 : 0; }
__device__ __forceinline__ int boff_of(int it) { return ((it >> 6) == 2) ? 4096 : 0; }

__device__ __forceinline__ void gemm_load_stage(
    const __nv_bfloat16* __restrict__ A, const __nv_bfloat16* __restrict__ Bt,
    int m0, int n0, int it, uint32_t sA, int tid)
{
    int kk = (it & 63) * BKK;
    int ka = aoff_of(it) + kk;
    int kb = boff_of(it) + kk;
    uint32_t sB = sA + 16384u;
#pragma unroll
    for (int u = 0; u < 4; u++) {
        int f = u * 256 + tid;
        int r = f >> 3;
        int c = f & 7;
        uint32_t sw = (uint32_t)(c ^ (r & 7));
        cp_async16(sA + (uint32_t)r * 128u + sw * 16u,
                   A + (size_t)(m0 + r) * K2 + ka + c * 8);
    }
#pragma unroll
    for (int u = 0; u < 4; u++) {
        int f = u * 256 + tid;
        int r = f >> 3;
        int c = f & 7;
        uint32_t sw = (uint32_t)(c ^ (r & 7));
        cp_async16(sB + (uint32_t)r * 128u + sw * 16u,
                   Bt + (size_t)(n0 + r) * K2 + kb + c * 8);
    }
    cp_commit();
}

__global__ __launch_bounds__(256, 2) void gemm_bf16_kernel(
    const __nv_bfloat16* __restrict__ A, const __nv_bfloat16* __restrict__ Bt,
    float* __restrict__ C, int N)
{
    extern __shared__ __align__(1024) char gsm[];
    const uint32_t sbase = smem_u32(gsm);
    const int tid  = threadIdx.x;
    const int wid  = tid >> 5;
    const int lane = tid & 31;

    const int m0 = blockIdx.x * 128;     // m fast-moving: wave shares B columns in L2
    const int n0 = blockIdx.y * 128;
    const int wm = (wid >> 2) * 64;
    const int wn = (wid & 3) * 32;

    float acc[4][4][4];
#pragma unroll
    for (int i = 0; i < 4; i++)
#pragma unroll
        for (int j = 0; j < 4; j++)
#pragma unroll
            for (int e = 0; e < 4; e++) acc[i][j][e] = 0.f;

    const int iters = 192;   // 3 terms x 64 iters of K=64
    gemm_load_stage(A, Bt, m0, n0, 0, sbase + 0u * STAGE_BYTES, tid);
    gemm_load_stage(A, Bt, m0, n0, 1, sbase + 1u * STAGE_BYTES, tid);

    const int a_row_in16 = ((lane >> 3) & 1) * 8 + (lane & 7);
    const int a_cadd     = lane >> 4;
    const int b_row_in8  = lane & 7;
    const int b_cadd     = (lane >> 3) & 1;

    for (int it = 0; it < iters; it++) {
        cp_wait<1>();
        __syncthreads();
        if (it + 2 < iters)
            gemm_load_stage(A, Bt, m0, n0, it + 2,
                            sbase + (uint32_t)((it + 2) % NST) * STAGE_BYTES, tid);

        uint32_t sA = sbase + (uint32_t)(it % NST) * STAGE_BYTES;
        uint32_t sB = sA + 16384u;

#pragma unroll
        for (int ks = 0; ks < 4; ks++) {
            int c0 = ks * 2;
            uint32_t afr[4][4];
#pragma unroll
            for (int im = 0; im < 4; im++) {
                int r  = wm + im * 16 + a_row_in16;
                int cc = c0 + a_cadd;
                uint32_t addr = sA + (uint32_t)r * 128u + (uint32_t)((cc ^ (r & 7)) * 16);
                ldmatrix_x4(afr[im], addr);
            }
            uint32_t bfr[4][2];
#pragma unroll
            for (int jn = 0; jn < 4; jn++) {
                int r  = wn + jn * 8 + b_row_in8;
                int cc = c0 + b_cadd;
                uint32_t addr = sB + (uint32_t)r * 128u + (uint32_t)((cc ^ (r & 7)) * 16);
                ldmatrix_x2(bfr[jn], addr);
            }
#pragma unroll
            for (int im = 0; im < 4; im++)
#pragma unroll
                for (int jn = 0; jn < 4; jn++)
                    mma_16816(acc[im][jn], afr[im], bfr[jn]);
        }
    }

    const int tg = lane >> 2;
    const int tc = lane & 3;
#pragma unroll
    for (int im = 0; im < 4; im++) {
#pragma unroll
        for (int jn = 0; jn < 4; jn++) {
            int row = m0 + wm + im * 16 + tg;
            int col = n0 + wn + jn * 8 + tc * 2;
            float2 v0 = make_float2(acc[im][jn][0], acc[im][jn][1]);
            float2 v1 = make_float2(acc[im][jn][2], acc[im][jn][3]);
            *(float2*)(C + (size_t)row * N + col) = v0;
            *(float2*)(C + (size_t)(row + 8) * N + col) = v1;
        }
    }
}

// =====================  RoPE table  =========================================
__global__ void rope_table_kernel() {
    int idx = blockIdx.x * blockDim.x + threadIdx.x;
    if (idx >= 2048 * 64) return;
    int p = idx >> 6;
    int i = idx & 63;
    double inv = exp(-((double)(2 * i) / (double)HD) * log(ROPE_THETA));
    double ang = (double)p * inv;
    g_cos[idx] = (float)cos(ang);
    g_sin[idx] = (float)sin(ang);
}

// =====================  Flash attention (mma.sync, split bf16)  =============
// CTA: 64 q-rows x 64 kv, 4 warps. K and V committed separately; V copy
// overlaps S computation.
#define FL_SMEM (6 * 16384 + 512)

__global__ __launch_bounds__(128) void flash_mma_kernel(
    const __nv_bfloat16* __restrict__ Qh, const __nv_bfloat16* __restrict__ Ql,
    const __nv_bfloat16* __restrict__ Kh, const __nv_bfloat16* __restrict__ Kl,
    const __nv_bfloat16* __restrict__ Vh, const __nv_bfloat16* __restrict__ Vl,
    const float* __restrict__ amask, float* __restrict__ O)
{
    extern __shared__ __align__(1024) char fsm[];
    const uint32_t sb = smem_u32(fsm);
    float* sMask = (float*)(fsm + 98304);

    const int tid  = threadIdx.x;
    const int warp = tid >> 5;
    const int lane = tid & 31;
    const int tg   = lane >> 2;
    const int tc   = lane & 3;
    const int qt   = (S_ / 64 - 1) - blockIdx.x;   // long tiles first
    const int h    = blockIdx.y;
    const int b    = blockIdx.z;
    const int kvh  = h >> 2;

    // ---- load Q tiles (hi, lo) ----
    {
        const __nv_bfloat16* qs[2] = {Qh, Ql};
#pragma unroll
        for (int t = 0; t < 16; t++) {
            int f = t * 128 + tid;
            int tile = t >> 3;
            int ft = f & 1023;
            int r = ft >> 4, c = ft & 15;
            uint32_t dst = sb + (uint32_t)tile * 16384u + (uint32_t)r * 256u +
                           (uint32_t)((c ^ (r & 7)) * 16);
            cp_async16(dst, qs[tile] + (size_t)(b * S_ + qt * 64 + r) * D_ + h * HD + c * 8);
        }
        cp_commit();
    }

    float acc_o[16][4];
#pragma unroll
    for (int i = 0; i < 16; i++)
#pragma unroll
        for (int e = 0; e < 4; e++) acc_o[i][e] = 0.f;
    float m0 = -INFINITY, m1 = -INFINITY, l0 = 0.f, l1 = 0.f;

    const int a_r16  = ((lane >> 3) & 1) * 8 + (lane & 7);
    const int a_cs   = lane >> 4;
    const int b_nsel = lane >> 4;
    const int b_row8 = lane & 7;
    const int b_cs   = (lane >> 3) & 1;
    const int v_half = (lane >> 3) & 1;
    const int v_sel  = lane >> 4;
    const int v_row7 = lane & 7;

    for (int kt = 0; kt <= qt; kt++) {
        if (kt) __syncthreads();     // all warps done reading prev K/V
        // ---- load K tiles (hi, lo) then V tiles, separate commit groups ----
        {
            const __nv_bfloat16* kvs[4] = {Kh, Kl, Vh, Vl};
#pragma unroll
            for (int t = 0; t < 16; t++) {
                int f = t * 128 + tid;
                int tile = t >> 3;
                int ft = f & 1023;
                int r = ft >> 4, c = ft & 15;
                uint32_t dst = sb + 32768u + (uint32_t)tile * 16384u + (uint32_t)r * 256u +
                               (uint32_t)((c ^ (r & 7)) * 16);
                cp_async16(dst, kvs[tile] + (size_t)(b * S_ + kt * 64 + r) * KVDIM + kvh * HD + c * 8);
            }
            cp_commit();
#pragma unroll
            for (int t = 16; t < 32; t++) {
                int f = t * 128 + tid;
                int tile = t >> 3;
                int ft = f & 1023;
                int r = ft >> 4, c = ft & 15;
                uint32_t dst = sb + 32768u + (uint32_t)tile * 16384u + (uint32_t)r * 256u +
                               (uint32_t)((c ^ (r & 7)) * 16);
                cp_async16(dst, kvs[tile] + (size_t)(b * S_ + kt * 64 + r) * KVDIM + kvh * HD + c * 8);
            }
            cp_commit();
        }
        if (tid < 64) sMask[tid] = amask[b * S_ + kt * 64 + tid];
        cp_wait<1>();                 // K (and Q on first iter) ready; V in flight
        __syncthreads();

        // ---- S = Q K^T (split: qh*kh + ql*kh + qh*kl) ----
        float accs[8][4];
#pragma unroll
        for (int nj = 0; nj < 8; nj++)
#pragma unroll
            for (int e = 0; e < 4; e++) accs[nj][e] = 0.f;

#pragma unroll
        for (int kc = 0; kc < 8; kc++) {
            uint32_t qh4[4], ql4[4];
            {
                int r = warp * 16 + a_r16;
                int cc = kc * 2 + a_cs;
                uint32_t off = (uint32_t)r * 256u + (uint32_t)((cc ^ (r & 7)) * 16);
                ldmatrix_x4(qh4, sb + off);
                ldmatrix_x4(ql4, sb + 16384u + off);
            }
#pragma unroll
            for (int njp = 0; njp < 4; njp++) {
                uint32_t kh4[4], kl4[4];
                int r = (njp * 2 + b_nsel) * 8 + b_row8;
                int cc = kc * 2 + b_cs;
                uint32_t off = (uint32_t)r * 256u + (uint32_t)((cc ^ (r & 7)) * 16);
                ldmatrix_x4(kh4, sb + 32768u + off);
                ldmatrix_x4(kl4, sb + 49152u + off);
                mma_16816(accs[2 * njp],     qh4, kh4);
                mma_16816(accs[2 * njp],     ql4, kh4);
                mma_16816(accs[2 * njp],     qh4, kl4);
                mma_16816(accs[2 * njp + 1], qh4, kh4 + 2);
                mma_16816(accs[2 * njp + 1], ql4, kh4 + 2);
                mma_16816(accs[2 * njp + 1], qh4, kl4 + 2);
            }
        }

        // ---- mask + online softmax ----
        const bool diag = (kt == qt);
        float mx0 = -INFINITY, mx1 = -INFINITY;
#pragma unroll
        for (int nj = 0; nj < 8; nj++) {
#pragma unroll
            for (int e = 0; e < 4; e++) {
                int kvl = nj * 8 + 2 * tc + (e & 1);
                bool valid = sMask[kvl] > 0.f;
                if (diag) {
                    int qloc = warp * 16 + tg + ((e >> 1) ? 8 : 0);
                    valid = valid && (kvl <= qloc);
                }
                float s = valid ? accs[nj][e] : -1e30f;
                accs[nj][e] = s;
                if (e < 2) mx0 = fmaxf(mx0, s); else mx1 = fmaxf(mx1, s);
            }
        }
        mx0 = fmaxf(mx0, __shfl_xor_sync(0xffffffffu, mx0, 1));
        mx0 = fmaxf(mx0, __shfl_xor_sync(0xffffffffu, mx0, 2));
        mx1 = fmaxf(mx1, __shfl_xor_sync(0xffffffffu, mx1, 1));
        mx1 = fmaxf(mx1, __shfl_xor_sync(0xffffffffu, mx1, 2));

        float mn0 = fmaxf(m0, mx0), mn1 = fmaxf(m1, mx1);
        float cr0 = __expf(m0 - mn0), cr1 = __expf(m1 - mn1);
        m0 = mn0; m1 = mn1;

        float s0 = 0.f, s1 = 0.f;
#pragma unroll
        for (int nj = 0; nj < 8; nj++) {
#pragma unroll
            for (int e = 0; e < 4; e++) {
                float p = __expf(accs[nj][e] - ((e < 2) ? m0 : m1));
                accs[nj][e] = p;
                if (e < 2) s0 += p; else s1 += p;
            }
        }
        s0 += __shfl_xor_sync(0xffffffffu, s0, 1);
        s0 += __shfl_xor_sync(0xffffffffu, s0, 2);
        s1 += __shfl_xor_sync(0xffffffffu, s1, 1);
        s1 += __shfl_xor_sync(0xffffffffu, s1, 2);
        l0 = l0 * cr0 + s0;
        l1 = l1 * cr1 + s1;

#pragma unroll
        for (int nd = 0; nd < 16; nd++) {
            acc_o[nd][0] *= cr0; acc_o[nd][1] *= cr0;
            acc_o[nd][2] *= cr1; acc_o[nd][3] *= cr1;
        }

        cp_wait<0>();                 // V now ready
        __syncthreads();

        // ---- O += P V (split: ph*vh + pl*vh + ph*vl) ----
#pragma unroll
        for (int kc2 = 0; kc2 < 4; kc2++) {
            float* p0 = accs[2 * kc2];
            float* p1 = accs[2 * kc2 + 1];
            uint32_t ah[4], al[4];
            ah[0] = pk_bf16x2(p0[0], p0[1]);
            ah[1] = pk_bf16x2(p0[2], p0[3]);
            ah[2] = pk_bf16x2(p1[0], p1[1]);
            ah[3] = pk_bf16x2(p1[2], p1[3]);
            {
                float2 f;
                f = unpk_bf16x2(ah[0]); al[0] = pk_bf16x2(p0[0] - f.x, p0[1] - f.y);
                f = unpk_bf16x2(ah[1]); al[1] = pk_bf16x2(p0[2] - f.x, p0[3] - f.y);
                f = unpk_bf16x2(ah[2]); al[2] = pk_bf16x2(p1[0] - f.x, p1[1] - f.y);
                f = unpk_bf16x2(ah[3]); al[3] = pk_bf16x2(p1[2] - f.x, p1[3] - f.y);
            }
            int vr = kc2 * 16 + v_half * 8 + v_row7;
#pragma unroll
            for (int ndp = 0; ndp < 8; ndp++) {
                int chunk = ndp * 2 + v_sel;
                uint32_t off = (uint32_t)vr * 256u + (uint32_t)((chunk ^ (vr & 7)) * 16);
                uint32_t bh4[4], bl4[4];
                ldmatrix_x4_trans(bh4, sb + 65536u + off);
                ldmatrix_x4_trans(bl4, sb + 81920u + off);
                mma_16816(acc_o[2 * ndp],     ah, bh4);
                mma_16816(acc_o[2 * ndp],     al, bh4);
                mma_16816(acc_o[2 * ndp],     ah, bl4);
                mma_16816(acc_o[2 * ndp + 1], ah, bh4 + 2);
                mma_16816(acc_o[2 * ndp + 1], al, bh4 + 2);
                mma_16816(acc_o[2 * ndp + 1], ah, bl4 + 2);
            }
        }
    }

    // ---- normalize + write ----
    float inv0 = 1.f / l0, inv1 = 1.f / l1;
    int row0 = b * S_ + qt * 64 + warp * 16 + tg;
#pragma unroll
    for (int nd = 0; nd < 16; nd++) {
        int col = h * HD + nd * 8 + 2 * tc;
        float2 v0 = make_float2(acc_o[nd][0] * inv0, acc_o[nd][1] * inv0);
        float2 v1 = make_float2(acc_o[nd][2] * inv1, acc_o[nd][3] * inv1);
        *(float2*)(O + (size_t)row0 * D_ + col) = v0;
        *(float2*)(O + (size_t)(row0 + 8) * D_ + col) = v1;
    }
}

// =====================  launch  =============================================
extern "C" void kernel_launch(void* const* d_in, const int* in_sizes, int n_in,
                              void* d_out, int out_size)
{
    const float* x     = (const float*)d_in[0];
    const float* amask = (const float*)d_in[1];
    const int*   pos   = (const int*)  d_in[2];
    const float* wq    = (const float*)d_in[3];
    const float* wk    = (const float*)d_in[4];
    const float* wv    = (const float*)d_in[5];
    const float* wo    = (const float*)d_in[6];
    float* out = (float*)d_out;

    float *qkv, *ao;
    __nv_bfloat16 *abf, *wbf;
    cudaGetSymbolAddress((void**)&qkv, g_qkv);
    cudaGetSymbolAddress((void**)&ao,  g_ao);
    cudaGetSymbolAddress((void**)&abf, g_Abf);
    cudaGetSymbolAddress((void**)&wbf, g_Wbf);

    __nv_bfloat16* wqkv_bf = wbf;                                // rows [0,6144)
    __nv_bfloat16* wo_bf   = wbf + (size_t)QKVN * K2;            // rows [0,4096)

    // flash split buffers aliased into g_Abf (free after fused GEMM reads it)
    const size_t QSZ = (size_t)MTOK * D_;
    const size_t KSZ = (size_t)MTOK * KVDIM;
    __nv_bfloat16* qh = abf;
    __nv_bfloat16* ql = qh + QSZ;
    __nv_bfloat16* kh = ql + QSZ;
    __nv_bfloat16* kl = kh + KSZ;
    __nv_bfloat16* vh = kl + KSZ;
    __nv_bfloat16* vl = vh + KSZ;

    cudaFuncSetAttribute(gemm_bf16_kernel, cudaFuncAttributeMaxDynamicSharedMemorySize, GEMM_SMEM);
    cudaFuncSetAttribute(flash_mma_kernel, cudaFuncAttributeMaxDynamicSharedMemorySize, FL_SMEM);

    // RoPE tables (2048 positions)
    rope_table_kernel<<<(2048 * 64) / 256, 256>>>();

    // Split-precision conversions
    convert_a_kernel<<<(MTOK * D_ / 4) / 256, 256>>>(x, abf);
    convert_w_kernel<<<dim3(D_ / 32,    D_ / 32), dim3(32, 8)>>>(wq, wqkv_bf, D_);
    convert_w_kernel<<<dim3(KVDIM / 32, D_ / 32), dim3(32, 8)>>>(wk, wqkv_bf + (size_t)4096 * K2, KVDIM);
    convert_w_kernel<<<dim3(KVDIM / 32, D_ / 32), dim3(32, 8)>>>(wv, wqkv_bf + (size_t)5120 * K2, KVDIM);
    convert_w_kernel<<<dim3(D_ / 32,    D_ / 32), dim3(32, 8)>>>(wo, wo_bf, D_);

    // Fused QKV projection (one GEMM, N=6144)
    gemm_bf16_kernel<<<dim3(MTOK / 128, QKVN / 128), 256, GEMM_SMEM>>>(abf, wqkv_bf, qkv, QKVN);

    // RoPE + scale + split (q, k), split (v)
    const float scale = 0.08838834764831845f;
    split_rope_kernel<<<(MTOK * 1024) / 256, 256>>>(qkv,        qh, ql, pos, scale, 10, QKVN, 1);
    split_rope_kernel<<<(MTOK * 256)  / 256, 256>>>(qkv + 4096, kh, kl, pos, 1.0f,  8,  QKVN, 1);
    split_rope_kernel<<<(MTOK * 256)  / 256, 256>>>(qkv + 5120, vh, vl, pos, 1.0f,  8,  QKVN, 0);

    // Attention (tensor-core flash)
    flash_mma_kernel<<<dim3(S_ / 64, NH, B_), 128, FL_SMEM>>>(qh, ql, kh, kl, vh, vl, amask, ao);

    // Output projection
    convert_a_kernel<<<(MTOK * D_ / 4) / 256, 256>>>(ao, abf);
    gemm_bf16_kernel<<<dim3(MTOK / 128, D_ / 128), 256, GEMM_SMEM>>>(abf, wo_bf, out, D_);
}

// round 7
// speedup vs baseline: 5.6272x; 1.4560x over previous
#include <cuda_runtime.h>
#include <cuda_fp16.h>
#include <cstdint>
#include <math.h>

// Problem constants
#define B_    2
#define S_    2048
#define D_    4096
#define NH    32
#define NKV   8
#define HD    128
#define MTOK  (B_*S_)          // 4096 tokens
#define KVDIM (NKV*HD)         // 1024
#define QKVN  (D_ + 2*KVDIM)   // 6144 fused projection width
#define K2    8192             // A operand: [hi|lo] fp16, width 8192
#define KW    4096             // W operand: single fp16, width 4096
#define ROPE_THETA 500000.0

// -------------------- scratch (device globals; no allocs allowed) -----------
__device__ float g_qkv[(size_t)MTOK * QKVN];   // fused QKV output fp32
__device__ float g_cos[2048 * 64];
__device__ float g_sin[2048 * 64];
__device__ float g_ao [(size_t)MTOK * D_];
// A operand (hi|lo fp16) for GEMMs; later aliased as flash split buffers
__device__ __half g_Abf[(size_t)MTOK * 12288];
// weights single fp16: [qkv rows 0..6144) | wo rows 6144..10240), row stride KW
__device__ __half g_Wbf[(size_t)10240 * KW];

// =====================  PTX helpers (baseline ISA only)  ====================
__device__ __forceinline__ uint32_t smem_u32(const void* p) {
    uint32_t a;
    asm("{ .reg .u64 t; cvta.to.shared.u64 t, %1; cvt.u32.u64 %0, t; }" : "=r"(a) : "l"(p));
    return a;
}
__device__ __forceinline__ void cp_async16(uint32_t s, const void* g) {
    asm volatile("cp.async.cg.shared.global [%0], [%1], 16;" :: "r"(s), "l"(g));
}
__device__ __forceinline__ void cp_commit() {
    asm volatile("cp.async.commit_group;" ::: "memory");
}
template<int N_> __device__ __forceinline__ void cp_wait() {
    asm volatile("cp.async.wait_group %0;" :: "n"(N_) : "memory");
}
__device__ __forceinline__ void ldmatrix_x4(uint32_t* r, uint32_t addr) {
    asm volatile("ldmatrix.sync.aligned.m8n8.x4.shared.b16 {%0,%1,%2,%3}, [%4];"
                 : "=r"(r[0]), "=r"(r[1]), "=r"(r[2]), "=r"(r[3]) : "r"(addr));
}
__device__ __forceinline__ void ldmatrix_x4_trans(uint32_t* r, uint32_t addr) {
    asm volatile("ldmatrix.sync.aligned.m8n8.x4.trans.shared.b16 {%0,%1,%2,%3}, [%4];"
                 : "=r"(r[0]), "=r"(r[1]), "=r"(r[2]), "=r"(r[3]) : "r"(addr));
}
__device__ __forceinline__ void mma_16816(float* d, const uint32_t* a, const uint32_t* b) {
    asm volatile(
        "mma.sync.aligned.m16n8k16.row.col.f32.f16.f16.f32 "
        "{%0,%1,%2,%3}, {%4,%5,%6,%7}, {%8,%9}, {%0,%1,%2,%3};"
        : "+f"(d[0]), "+f"(d[1]), "+f"(d[2]), "+f"(d[3])
        : "r"(a[0]), "r"(a[1]), "r"(a[2]), "r"(a[3]), "r"(b[0]), "r"(b[1]));
}
__device__ __forceinline__ uint32_t pk_f16x2(float lo, float hi) {
    uint32_t d;
    asm("cvt.rn.f16x2.f32 %0, %1, %2;" : "=r"(d) : "f"(hi), "f"(lo));
    return d;
}
__device__ __forceinline__ float2 unpk_f16x2(uint32_t u) {
    __half2 h = *(__half2*)&u;
    return __half22float2(h);
}

// =====================  conversion kernels  =================================
// X[4096][4096] fp32 -> Y[4096][K2] fp16: [0,4096)=hi, [4096,8192)=lo (exact split)
__global__ __launch_bounds__(256) void convert_a_kernel(const float* __restrict__ X,
                                                        __half* __restrict__ Y) {
    int i = blockIdx.x * blockDim.x + threadIdx.x;
    int row = i >> 10;
    int col = (i & 1023) << 2;
    float4 v = ((const float4*)X)[i];
    __half hx = __float2half_rn(v.x);
    __half hy = __float2half_rn(v.y);
    __half hz = __float2half_rn(v.z);
    __half hw = __float2half_rn(v.w);
    __half lx = __float2half_rn(v.x - __half2float(hx));
    __half ly = __float2half_rn(v.y - __half2float(hy));
    __half lz = __float2half_rn(v.z - __half2float(hz));
    __half lw = __float2half_rn(v.w - __half2float(hw));
    size_t base = (size_t)row * K2 + col;
    ((__half2*)(Y + base))[0] = __halves2half2(hx, hy);
    ((__half2*)(Y + base))[1] = __halves2half2(hz, hw);
    ((__half2*)(Y + base + 4096))[0] = __halves2half2(lx, ly);
    ((__half2*)(Y + base + 4096))[1] = __halves2half2(lz, lw);
}

// W[K=4096][N] fp32 -> Y[N][KW] fp16 single, transposed
__global__ __launch_bounds__(256) void convert_w_kernel(const float* __restrict__ W,
                                                        __half* __restrict__ Y, int N) {
    __shared__ float t[32][33];
    int n0 = blockIdx.x * 32;
    int k0 = blockIdx.y * 32;
    int tx = threadIdx.x;
    int ty = threadIdx.y;
#pragma unroll
    for (int i = 0; i < 4; i++)
        t[ty + 8 * i][tx] = W[(size_t)(k0 + ty + 8 * i) * N + n0 + tx];
    __syncthreads();
#pragma unroll
    for (int i = 0; i < 4; i++) {
        int r = ty + 8 * i;
        Y[(size_t)(n0 + r) * KW + k0 + tx] = __float2half_rn(t[tx][r]);
    }
}

// fused rope + scale + split: X (strided fp32) -> compact H (fp16), optional L
__global__ __launch_bounds__(256) void split_rope_kernel(
    const float* __restrict__ X, __half* __restrict__ H,
    __half* __restrict__ L, const int* __restrict__ pos,
    float scale, int rl_shift, int srcStride, int do_rope)
{
    int i = blockIdx.x * blockDim.x + threadIdx.x;
    int row = i >> rl_shift;
    int c4 = (i & ((1 << rl_shift) - 1)) << 2;
    float4 v = *(const float4*)(X + (size_t)row * srcStride + c4);
    if (do_rope) {
        int p = pos[row];
        int i0 = (c4 & 127) >> 1;
        float c0 = g_cos[p * 64 + i0],     s0 = g_sin[p * 64 + i0];
        float c1 = g_cos[p * 64 + i0 + 1], s1 = g_sin[p * 64 + i0 + 1];
        float ax = v.x, bx = v.y, az = v.z, bw = v.w;
        v.x = ax * c0 - bx * s0;
        v.y = ax * s0 + bx * c0;
        v.z = az * c1 - bw * s1;
        v.w = az * s1 + bw * c1;
    }
    v.x *= scale; v.y *= scale; v.z *= scale; v.w *= scale;
    __half hx = __float2half_rn(v.x);
    __half hy = __float2half_rn(v.y);
    __half hz = __float2half_rn(v.z);
    __half hw = __float2half_rn(v.w);
    size_t base = ((size_t)row << (rl_shift + 2)) + c4;
    ((__half2*)(H + base))[0] = __halves2half2(hx, hy);
    ((__half2*)(H + base))[1] = __halves2half2(hz, hw);
    if (L != nullptr) {
        __half lx = __float2half_rn(v.x - __half2float(hx));
        __half ly = __float2half_rn(v.y - __half2float(hy));
        __half lz = __float2half_rn(v.z - __half2float(hz));
        __half lw = __float2half_rn(v.w - __half2float(hw));
        ((__half2*)(L + base))[0] = __halves2half2(lx, ly);
        ((__half2*)(L + base))[1] = __halves2half2(lz, lw);
    }
}

// =====================  mma.sync fp16 GEMM (2-term split A, single W)  ======
#define BKK 64
#define NST 3
#define STAGE_BYTES 32768
#define GEMM_SMEM (NST * STAGE_BYTES)

__device__ __forceinline__ void gemm_load_stage(
    const __half* __restrict__ A, const __half* __restrict__ Bt,
    int m0, int n0, int it, uint32_t sA, int tid)
{
    int kk = (it & 63) * BKK;
    int ka = ((it >> 6) & 1) * 4096 + kk;   // term 0: ah, term 1: al
    uint32_t sB = sA + 16384u;
#pragma unroll
    for (int u = 0; u < 4; u++) {
        int f = u * 256 + tid;
        int r = f >> 3;
        int c = f & 7;
        uint32_t sw = (uint32_t)(c ^ (r & 7));
        cp_async16(sA + (uint32_t)r * 128u + sw * 16u,
                   A + (size_t)(m0 + r) * K2 + ka + c * 8);
    }
#pragma unroll
    for (int u = 0; u < 4; u++) {
        int f = u * 256 + tid;
        int r = f >> 3;
        int c = f & 7;
        uint32_t sw = (uint32_t)(c ^ (r & 7));
        cp_async16(sB + (uint32_t)r * 128u + sw * 16u,
                   Bt + (size_t)(n0 + r) * KW + kk + c * 8);
    }
    cp_commit();
}

__global__ __launch_bounds__(256, 2) void gemm_f16_kernel(
    const __half* __restrict__ A, const __half* __restrict__ Bt,
    float* __restrict__ C, int N)
{
    extern __shared__ __align__(1024) char gsm[];
    const uint32_t sbase = smem_u32(gsm);
    const int tid  = threadIdx.x;
    const int wid  = tid >> 5;
    const int lane = tid & 31;

    const int m0 = blockIdx.x * 128;     // m fast-moving: wave shares B columns in L2
    const int n0 = blockIdx.y * 128;
    const int wm = (wid >> 2) * 64;
    const int wn = (wid & 3) * 32;

    float acc[4][4][4];
#pragma unroll
    for (int i = 0; i < 4; i++)
#pragma unroll
        for (int j = 0; j < 4; j++)
#pragma unroll
            for (int e = 0; e < 4; e++) acc[i][j][e] = 0.f;

    const int iters = 128;   // 2 terms x 64 iters of K=64
    gemm_load_stage(A, Bt, m0, n0, 0, sbase + 0u * STAGE_BYTES, tid);
    gemm_load_stage(A, Bt, m0, n0, 1, sbase + 1u * STAGE_BYTES, tid);

    const int a_row_in16 = ((lane >> 3) & 1) * 8 + (lane & 7);
    const int a_cadd     = lane >> 4;
    const int b_sel      = lane >> 4;
    const int b_row8     = lane & 7;
    const int b_cs       = (lane >> 3) & 1;

    for (int it = 0; it < iters; it++) {
        cp_wait<1>();
        __syncthreads();
        if (it + 2 < iters)
            gemm_load_stage(A, Bt, m0, n0, it + 2,
                            sbase + (uint32_t)((it + 2) % NST) * STAGE_BYTES, tid);

        uint32_t sA = sbase + (uint32_t)(it % NST) * STAGE_BYTES;
        uint32_t sB = sA + 16384u;

#pragma unroll
        for (int ks = 0; ks < 4; ks++) {
            int c0 = ks * 2;
            uint32_t afr[4][4];
#pragma unroll
            for (int im = 0; im < 4; im++) {
                int r  = wm + im * 16 + a_row_in16;
                int cc = c0 + a_cadd;
                uint32_t addr = sA + (uint32_t)r * 128u + (uint32_t)((cc ^ (r & 7)) * 16);
                ldmatrix_x4(afr[im], addr);
            }
            uint32_t bfr[2][4];
#pragma unroll
            for (int njp = 0; njp < 2; njp++) {
                int r  = wn + (njp * 2 + b_sel) * 8 + b_row8;
                int cc = c0 + b_cs;
                uint32_t addr = sB + (uint32_t)r * 128u + (uint32_t)((cc ^ (r & 7)) * 16);
                ldmatrix_x4(bfr[njp], addr);
            }
#pragma unroll
            for (int im = 0; im < 4; im++)
#pragma unroll
                for (int njp = 0; njp < 2; njp++) {
                    mma_16816(acc[im][2 * njp],     afr[im], bfr[njp]);
                    mma_16816(acc[im][2 * njp + 1], afr[im], bfr[njp] + 2);
                }
        }
    }

    const int tg = lane >> 2;
    const int tc = lane & 3;
#pragma unroll
    for (int im = 0; im < 4; im++) {
#pragma unroll
        for (int jn = 0; jn < 4; jn++) {
            int row = m0 + wm + im * 16 + tg;
            int col = n0 + wn + jn * 8 + tc * 2;
            float2 v0 = make_float2(acc[im][jn][0], acc[im][jn][1]);
            float2 v1 = make_float2(acc[im][jn][2], acc[im][jn][3]);
            *(float2*)(C + (size_t)row * N + col) = v0;
            *(float2*)(C + (size_t)(row + 8) * N + col) = v1;
        }
    }
}

// =====================  RoPE table  =========================================
__global__ void rope_table_kernel() {
    int idx = blockIdx.x * blockDim.x + threadIdx.x;
    if (idx >= 2048 * 64) return;
    int p = idx >> 6;
    int i = idx & 63;
    double inv = exp(-((double)(2 * i) / (double)HD) * log(ROPE_THETA));
    double ang = (double)p * inv;
    g_cos[idx] = (float)cos(ang);
    g_sin[idx] = (float)sin(ang);
}

// =====================  Flash attention (mma.sync fp16, 2-term)  ============
// CTA: 64 q-rows x 64 kv, 4 warps. Tiles: Qh(0) Ql(16K) Kh(32K) Vh(48K), mask @64K.
#define FL_SMEM (4 * 16384 + 512)

__global__ __launch_bounds__(128) void flash_mma_kernel(
    const __half* __restrict__ Qh, const __half* __restrict__ Ql,
    const __half* __restrict__ Kh, const __half* __restrict__ Vh,
    const float* __restrict__ amask, float* __restrict__ O)
{
    extern __shared__ __align__(1024) char fsm[];
    const uint32_t sb = smem_u32(fsm);
    float* sMask = (float*)(fsm + 65536);

    const int tid  = threadIdx.x;
    const int warp = tid >> 5;
    const int lane = tid & 31;
    const int tg   = lane >> 2;
    const int tc   = lane & 3;
    const int qt   = (S_ / 64 - 1) - blockIdx.x;   // long tiles first
    const int h    = blockIdx.y;
    const int b    = blockIdx.z;
    const int kvh  = h >> 2;

    // ---- load Q tiles (hi, lo) ----
    {
        const __half* qs[2] = {Qh, Ql};
#pragma unroll
        for (int t = 0; t < 16; t++) {
            int f = t * 128 + tid;
            int tile = t >> 3;
            int ft = f & 1023;
            int r = ft >> 4, c = ft & 15;
            uint32_t dst = sb + (uint32_t)tile * 16384u + (uint32_t)r * 256u +
                           (uint32_t)((c ^ (r & 7)) * 16);
            cp_async16(dst, qs[tile] + (size_t)(b * S_ + qt * 64 + r) * D_ + h * HD + c * 8);
        }
        cp_commit();
    }

    float acc_o[16][4];
#pragma unroll
    for (int i = 0; i < 16; i++)
#pragma unroll
        for (int e = 0; e < 4; e++) acc_o[i][e] = 0.f;
    float m0 = -INFINITY, m1 = -INFINITY, l0 = 0.f, l1 = 0.f;

    const int a_r16  = ((lane >> 3) & 1) * 8 + (lane & 7);
    const int a_cs   = lane >> 4;
    const int b_nsel = lane >> 4;
    const int b_row8 = lane & 7;
    const int b_cs   = (lane >> 3) & 1;
    const int v_half = (lane >> 3) & 1;
    const int v_sel  = lane >> 4;
    const int v_row7 = lane & 7;

    for (int kt = 0; kt <= qt; kt++) {
        if (kt) __syncthreads();     // all warps done reading prev K/V
        // ---- load K tile then V tile, separate commit groups ----
        {
#pragma unroll
            for (int t = 0; t < 8; t++) {
                int f = t * 128 + tid;
                int r = f >> 4, c = f & 15;
                uint32_t dst = sb + 32768u + (uint32_t)r * 256u +
                               (uint32_t)((c ^ (r & 7)) * 16);
                cp_async16(dst, Kh + (size_t)(b * S_ + kt * 64 + r) * KVDIM + kvh * HD + c * 8);
            }
            cp_commit();
#pragma unroll
            for (int t = 0; t < 8; t++) {
                int f = t * 128 + tid;
                int r = f >> 4, c = f & 15;
                uint32_t dst = sb + 49152u + (uint32_t)r * 256u +
                               (uint32_t)((c ^ (r & 7)) * 16);
                cp_async16(dst, Vh + (size_t)(b * S_ + kt * 64 + r) * KVDIM + kvh * HD + c * 8);
            }
            cp_commit();
        }
        if (tid < 64) sMask[tid] = amask[b * S_ + kt * 64 + tid];
        cp_wait<1>();                 // K (and Q on first iter) ready; V in flight
        __syncthreads();

        // ---- S = Q K^T (qh*kh + ql*kh) ----
        float accs[8][4];
#pragma unroll
        for (int nj = 0; nj < 8; nj++)
#pragma unroll
            for (int e = 0; e < 4; e++) accs[nj][e] = 0.f;

#pragma unroll
        for (int kc = 0; kc < 8; kc++) {
            uint32_t qh4[4], ql4[4];
            {
                int r = warp * 16 + a_r16;
                int cc = kc * 2 + a_cs;
                uint32_t off = (uint32_t)r * 256u + (uint32_t)((cc ^ (r & 7)) * 16);
                ldmatrix_x4(qh4, sb + off);
                ldmatrix_x4(ql4, sb + 16384u + off);
            }
#pragma unroll
            for (int njp = 0; njp < 4; njp++) {
                uint32_t kh4[4];
                int r = (njp * 2 + b_nsel) * 8 + b_row8;
                int cc = kc * 2 + b_cs;
                uint32_t off = (uint32_t)r * 256u + (uint32_t)((cc ^ (r & 7)) * 16);
                ldmatrix_x4(kh4, sb + 32768u + off);
                mma_16816(accs[2 * njp],     qh4, kh4);
                mma_16816(accs[2 * njp],     ql4, kh4);
                mma_16816(accs[2 * njp + 1], qh4, kh4 + 2);
                mma_16816(accs[2 * njp + 1], ql4, kh4 + 2);
            }
        }

        // ---- mask + online softmax ----
        const bool diag = (kt == qt);
        float mx0 = -INFINITY, mx1 = -INFINITY;
#pragma unroll
        for (int nj = 0; nj < 8; nj++) {
#pragma unroll
            for (int e = 0; e < 4; e++) {
                int kvl = nj * 8 + 2 * tc + (e & 1);
                bool valid = sMask[kvl] > 0.f;
                if (diag) {
                    int qloc = warp * 16 + tg + ((e >> 1) ? 8 : 0);
                    valid = valid && (kvl <= qloc);
                }
                float s = valid ? accs[nj][e] : -1e30f;
                accs[nj][e] = s;
                if (e < 2) mx0 = fmaxf(mx0, s); else mx1 = fmaxf(mx1, s);
            }
        }
        mx0 = fmaxf(mx0, __shfl_xor_sync(0xffffffffu, mx0, 1));
        mx0 = fmaxf(mx0, __shfl_xor_sync(0xffffffffu, mx0, 2));
        mx1 = fmaxf(mx1, __shfl_xor_sync(0xffffffffu, mx1, 1));
        mx1 = fmaxf(mx1, __shfl_xor_sync(0xffffffffu, mx1, 2));

        float mn0 = fmaxf(m0, mx0), mn1 = fmaxf(m1, mx1);
        float cr0 = __expf(m0 - mn0), cr1 = __expf(m1 - mn1);
        m0 = mn0; m1 = mn1;

        float s0 = 0.f, s1 = 0.f;
#pragma unroll
        for (int nj = 0; nj < 8; nj++) {
#pragma unroll
            for (int e = 0; e < 4; e++) {
                float p = __expf(accs[nj][e] - ((e < 2) ? m0 : m1));
                accs[nj][e] = p;
                if (e < 2) s0 += p; else s1 += p;
            }
        }
        s0 += __shfl_xor_sync(0xffffffffu, s0, 1);
        s0 += __shfl_xor_sync(0xffffffffu, s0, 2);
        s1 += __shfl_xor_sync(0xffffffffu, s1, 1);
        s1 += __shfl_xor_sync(0xffffffffu, s1, 2);
        l0 = l0 * cr0 + s0;
        l1 = l1 * cr1 + s1;

#pragma unroll
        for (int nd = 0; nd < 16; nd++) {
            acc_o[nd][0] *= cr0; acc_o[nd][1] *= cr0;
            acc_o[nd][2] *= cr1; acc_o[nd][3] *= cr1;
        }

        cp_wait<0>();                 // V now ready
        __syncthreads();

        // ---- O += P V (ph*vh + pl*vh) ----
#pragma unroll
        for (int kc2 = 0; kc2 < 4; kc2++) {
            float* p0 = accs[2 * kc2];
            float* p1 = accs[2 * kc2 + 1];
            uint32_t ah[4], al[4];
            ah[0] = pk_f16x2(p0[0], p0[1]);
            ah[1] = pk_f16x2(p0[2], p0[3]);
            ah[2] = pk_f16x2(p1[0], p1[1]);
            ah[3] = pk_f16x2(p1[2], p1[3]);
            {
                float2 f;
                f = unpk_f16x2(ah[0]); al[0] = pk_f16x2(p0[0] - f.x, p0[1] - f.y);
                f = unpk_f16x2(ah[1]); al[1] = pk_f16x2(p0[2] - f.x, p0[3] - f.y);
                f = unpk_f16x2(ah[2]); al[2] = pk_f16x2(p1[0] - f.x, p1[1] - f.y);
                f = unpk_f16x2(ah[3]); al[3] = pk_f16x2(p1[2] - f.x, p1[3] - f.y);
            }
            int vr = kc2 * 16 + v_half * 8 + v_row7;
#pragma unroll
            for (int ndp = 0; ndp < 8; ndp++) {
                int chunk = ndp * 2 + v_sel;
                uint32_t off = (uint32_t)vr * 256u + (uint32_t)((chunk ^ (vr & 7)) * 16);
                uint32_t bh4[4];
                ldmatrix_x4_trans(bh4, sb + 49152u + off);
                mma_16816(acc_o[2 * ndp],     ah, bh4);
                mma_16816(acc_o[2 * ndp],     al, bh4);
                mma_16816(acc_o[2 * ndp + 1], ah, bh4 + 2);
                mma_16816(acc_o[2 * ndp + 1], al, bh4 + 2);
            }
        }
    }

    // ---- normalize + write ----
    float inv0 = 1.f / l0, inv1 = 1.f / l1;
    int row0 = b * S_ + qt * 64 + warp * 16 + tg;
#pragma unroll
    for (int nd = 0; nd < 16; nd++) {
        int col = h * HD + nd * 8 + 2 * tc;
        float2 v0 = make_float2(acc_o[nd][0] * inv0, acc_o[nd][1] * inv0);
        float2 v1 = make_float2(acc_o[nd][2] * inv1, acc_o[nd][3] * inv1);
        *(float2*)(O + (size_t)row0 * D_ + col) = v0;
        *(float2*)(O + (size_t)(row0 + 8) * D_ + col) = v1;
    }
}

// =====================  launch  =============================================
extern "C" void kernel_launch(void* const* d_in, const int* in_sizes, int n_in,
                              void* d_out, int out_size)
{
    const float* x     = (const float*)d_in[0];
    const float* amask = (const float*)d_in[1];
    const int*   pos   = (const int*)  d_in[2];
    const float* wq    = (const float*)d_in[3];
    const float* wk    = (const float*)d_in[4];
    const float* wv    = (const float*)d_in[5];
    const float* wo    = (const float*)d_in[6];
    float* out = (float*)d_out;

    float *qkv, *ao;
    __half *abf, *wbf;
    cudaGetSymbolAddress((void**)&qkv, g_qkv);
    cudaGetSymbolAddress((void**)&ao,  g_ao);
    cudaGetSymbolAddress((void**)&abf, g_Abf);
    cudaGetSymbolAddress((void**)&wbf, g_Wbf);

    __half* wqkv_h = wbf;                              // rows [0,6144)
    __half* wo_h   = wbf + (size_t)QKVN * KW;          // rows [0,4096)

    // flash split buffers aliased into g_Abf (free after fused GEMM reads it)
    const size_t QSZ = (size_t)MTOK * D_;
    const size_t KSZ = (size_t)MTOK * KVDIM;
    __half* qh = abf;
    __half* ql = qh + QSZ;
    __half* kh = ql + QSZ;
    __half* vh = kh + KSZ;

    cudaFuncSetAttribute(gemm_f16_kernel, cudaFuncAttributeMaxDynamicSharedMemorySize, GEMM_SMEM);
    cudaFuncSetAttribute(flash_mma_kernel, cudaFuncAttributeMaxDynamicSharedMemorySize, FL_SMEM);

    // RoPE tables (2048 positions)
    rope_table_kernel<<<(2048 * 64) / 256, 256>>>();

    // Conversions: A split fp16, weights single fp16 transposed
    convert_a_kernel<<<(MTOK * D_ / 4) / 256, 256>>>(x, abf);
    convert_w_kernel<<<dim3(D_ / 32,    D_ / 32), dim3(32, 8)>>>(wq, wqkv_h, D_);
    convert_w_kernel<<<dim3(KVDIM / 32, D_ / 32), dim3(32, 8)>>>(wk, wqkv_h + (size_t)4096 * KW, KVDIM);
    convert_w_kernel<<<dim3(KVDIM / 32, D_ / 32), dim3(32, 8)>>>(wv, wqkv_h + (size_t)5120 * KW, KVDIM);
    convert_w_kernel<<<dim3(D_ / 32,    D_ / 32), dim3(32, 8)>>>(wo, wo_h, D_);

    // Fused QKV projection (one GEMM, N=6144)
    gemm_f16_kernel<<<dim3(MTOK / 128, QKVN / 128), 256, GEMM_SMEM>>>(abf, wqkv_h, qkv, QKVN);

    // RoPE + scale + split (q: hi+lo), rope (k: hi only), plain (v: hi only)
    const float scale = 0.08838834764831845f;
    split_rope_kernel<<<(MTOK * 1024) / 256, 256>>>(qkv,        qh, ql,     pos, scale, 10, QKVN, 1);
    split_rope_kernel<<<(MTOK * 256)  / 256, 256>>>(qkv + 4096, kh, nullptr, pos, 1.0f,  8,  QKVN, 1);
    split_rope_kernel<<<(MTOK * 256)  / 256, 256>>>(qkv + 5120, vh, nullptr, pos, 1.0f,  8,  QKVN, 0);

    // Attention (tensor-core flash)
    flash_mma_kernel<<<dim3(S_ / 64, NH, B_), 128, FL_SMEM>>>(qh, ql, kh, vh, amask, ao);

    // Output projection
    convert_a_kernel<<<(MTOK * D_ / 4) / 256, 256>>>(ao, abf);
    gemm_f16_kernel<<<dim3(MTOK / 128, D_ / 128), 256, GEMM_SMEM>>>(abf, wo_h, out, D_);
}